// round 10
// baseline (speedup 1.0000x reference)
#include <cuda_runtime.h>
#include <cuda_bf16.h>
#include <cstdint>
#include <cstddef>

// ---------------------------------------------------------------------------
// Problem constants
// ---------------------------------------------------------------------------
#define Bdim  8
#define Fdim  16
#define Pdim  196
#define Ddim  768
#define Hh    12
#define HD    64
#define Ndim  3136              // F*P
#define Mrows 25088             // B*N
#define E3    2304              // 3*D

#define HEAD_ELEMS ((size_t)Bdim * Hh * Ndim * HD)
#define MD_ELEMS   ((size_t)Mrows * Ddim)

// Scratch (__device__ globals; allocation-free rule)
__device__ float g_q[HEAD_ELEMS];
__device__ float g_k[HEAD_ELEMS];
__device__ float g_v[HEAD_ELEMS];

__device__ __nv_bfloat16 g_xhi[MD_ELEMS];
__device__ __nv_bfloat16 g_xlo[MD_ELEMS];
__device__ __nv_bfloat16 g_wqkv_hi[(size_t)E3 * Ddim];
__device__ __nv_bfloat16 g_wqkv_lo[(size_t)E3 * Ddim];
__device__ __nv_bfloat16 g_wproj_hi[(size_t)Ddim * Ddim];
__device__ __nv_bfloat16 g_wproj_lo[(size_t)Ddim * Ddim];
__device__ __nv_bfloat16 g_wf_hi[MD_ELEMS];
__device__ __nv_bfloat16 g_wf_lo[MD_ELEMS];

// ---------------------------------------------------------------------------
// helpers
// ---------------------------------------------------------------------------
__device__ __forceinline__ void cp_async16(uint32_t dst, const void* src) {
    asm volatile("cp.async.cg.shared.global [%0], [%1], 16;"
                 :: "r"(dst), "l"(src) : "memory");
}
#define CP_COMMIT() asm volatile("cp.async.commit_group;" ::: "memory")
template <int N> __device__ __forceinline__ void cp_wait() {
    asm volatile("cp.async.wait_group %0;" :: "n"(N) : "memory");
}
__device__ __forceinline__ uint32_t smem_u32(const void* p) {
    uint32_t a;
    asm("{ .reg .u64 t; cvta.to.shared.u64 t, %1; cvt.u32.u64 %0, t; }"
        : "=r"(a) : "l"(p));
    return a;
}

__device__ __forceinline__ void mma16816(float* d,
                                         uint32_t a0, uint32_t a1, uint32_t a2, uint32_t a3,
                                         uint32_t b0, uint32_t b1) {
    asm volatile(
        "mma.sync.aligned.m16n8k16.row.col.f32.bf16.bf16.f32 "
        "{%0,%1,%2,%3}, {%4,%5,%6,%7}, {%8,%9}, {%0,%1,%2,%3};"
        : "+f"(d[0]), "+f"(d[1]), "+f"(d[2]), "+f"(d[3])
        : "r"(a0), "r"(a1), "r"(a2), "r"(a3), "r"(b0), "r"(b1));
}

__device__ __forceinline__ void ldsm4(uint32_t& r0, uint32_t& r1,
                                      uint32_t& r2, uint32_t& r3, uint32_t addr) {
    asm volatile("ldmatrix.sync.aligned.m8n8.x4.shared.b16 {%0,%1,%2,%3}, [%4];"
                 : "=r"(r0), "=r"(r1), "=r"(r2), "=r"(r3) : "r"(addr));
}

// ---------------------------------------------------------------------------
// HMMA GEMM:  C = (Ahi+Alo)[M,768] * (Bhi+Blo)[N,768]^T
// 128x128x16 CTA tile, 256 threads, warp grid 2(M)x4(N), warp tile 64x32.
// 4-stage cp.async pipeline, depth 2 (cp_wait<2>): chunk c computes while
// c+1 and c+2 are in flight. LDK=24 (48B rows): ldmatrix row addrs mod 128B
// = {0,48,96,16,64,112,32,80} -> conflict-free. 98.3KB smem -> 2 CTAs/SM.
// mode 0: scatter epilogue into q/k/v head layout (no bias)
// mode 1: normal C[M,Nd] + bias
// ---------------------------------------------------------------------------
#define BK       16
#define LDK      24                       // padded row length (bf16)
#define TILE_B   (128 * LDK * 2)          // 6144 bytes per matrix tile
#define STAGE_B  (4 * TILE_B)             // Ahi, Alo, Bhi, Blo = 24576
#define NSTAGE   4
#define GSMEM    (NSTAGE * STAGE_B)       // 98304
#define OFF_AHI  0
#define OFF_ALO  TILE_B
#define OFF_BHI  (2 * TILE_B)
#define OFF_BLO  (3 * TILE_B)

__global__ __launch_bounds__(256, 2) void tgemm_k(
    const __nv_bfloat16* __restrict__ Ahi, const __nv_bfloat16* __restrict__ Alo,
    const __nv_bfloat16* __restrict__ Bhi, const __nv_bfloat16* __restrict__ Blo,
    const float* __restrict__ bias, float* __restrict__ C, int Nd, int mode,
    float* __restrict__ Qo, float* __restrict__ Ko, float* __restrict__ Vo)
{
    extern __shared__ char smem[];
    const uint32_t sb = smem_u32(smem);

    const int tid  = threadIdx.x;
    const int lane = tid & 31;
    const int wid  = tid >> 5;
    const int wm   = wid & 1;          // 0..1 : M
    const int wn   = wid >> 1;         // 0..3 : N
    const int g    = lane >> 2;        // 0..7
    const int tg   = lane & 3;         // 0..3

    const int bm = blockIdx.y * 128;
    const int bn = blockIdx.x * 128;

    // ldmatrix per-lane address components
    const int a_row = wm * 64 + (lane & 15);        // + mt*16
    const int a_kc  = (lane >> 4) * 8;
    const int b_row = wn * 32 + ((lane >> 4) << 3) + (lane & 7);  // + p*16
    const int b_kc  = ((lane >> 3) & 1) * 8;

    // gmem->smem loader role: 4 tiles x 64 threads, 4 granules (16B) each
    const int tile = tid >> 6;         // 0:Ahi 1:Alo 2:Bhi 3:Blo
    const int lt   = tid & 63;
    const __nv_bfloat16* src_base =
        (tile == 0) ? Ahi : (tile == 1) ? Alo : (tile == 2) ? Bhi : Blo;
    const int rowbase = (tile < 2) ? bm : bn;
    const uint32_t tile_off = tile * TILE_B;

    auto load_chunk = [&](int k0, int stage) {
        const uint32_t dbase = sb + stage * STAGE_B + tile_off;
#pragma unroll
        for (int j = 0; j < 4; j++) {
            int id  = lt + j * 64;          // 0..255
            int row = id >> 1;              // 0..127
            int gr  = id & 1;               // 16B granule within 32B row
            const void* src = src_base + (size_t)(rowbase + row) * Ddim + k0 + gr * 8;
            cp_async16(dbase + (uint32_t)(row * (LDK * 2) + gr * 16), src);
        }
        CP_COMMIT();
    };

    float acc[4][4][4];
#pragma unroll
    for (int i = 0; i < 4; i++)
#pragma unroll
        for (int j = 0; j < 4; j++)
#pragma unroll
            for (int q = 0; q < 4; q++) acc[i][j][q] = 0.f;

    load_chunk(0, 0);
    load_chunk(BK, 1);
    load_chunk(2 * BK, 2);

    const int NCH = Ddim / BK;   // 48
    for (int c = 0; c < NCH; c++) {
        if (c <= NCH - 3)      cp_wait<2>();
        else if (c == NCH - 2) cp_wait<1>();
        else                   cp_wait<0>();
        __syncthreads();
        if (c + 3 < NCH) load_chunk((c + 3) * BK, (c + 3) % NSTAGE);

        const uint32_t st = sb + (c % NSTAGE) * STAGE_B;

        uint32_t ah[4][4], al[4][4];
#pragma unroll
        for (int mt = 0; mt < 4; mt++) {
            uint32_t addr = st + (uint32_t)(((a_row + mt * 16) * LDK + a_kc) * 2);
            ldsm4(ah[mt][0], ah[mt][1], ah[mt][2], ah[mt][3], addr + OFF_AHI);
            ldsm4(al[mt][0], al[mt][1], al[mt][2], al[mt][3], addr + OFF_ALO);
        }
#pragma unroll
        for (int p = 0; p < 2; p++) {
            uint32_t baddr = st + (uint32_t)(((b_row + p * 16) * LDK + b_kc) * 2);
            uint32_t bh[2][2], bl[2][2];
            ldsm4(bh[0][0], bh[0][1], bh[1][0], bh[1][1], baddr + OFF_BHI);
            ldsm4(bl[0][0], bl[0][1], bl[1][0], bl[1][1], baddr + OFF_BLO);
#pragma unroll
            for (int q = 0; q < 2; q++) {
                const int nt = p * 2 + q;
#pragma unroll
                for (int mt = 0; mt < 4; mt++) {
                    mma16816(acc[mt][nt], ah[mt][0], ah[mt][1], ah[mt][2], ah[mt][3],
                             bh[q][0], bh[q][1]);
                    mma16816(acc[mt][nt], ah[mt][0], ah[mt][1], ah[mt][2], ah[mt][3],
                             bl[q][0], bl[q][1]);
                    mma16816(acc[mt][nt], al[mt][0], al[mt][1], al[mt][2], al[mt][3],
                             bh[q][0], bh[q][1]);
                }
            }
        }
    }

    // epilogue
    if (mode == 1) {
#pragma unroll
        for (int mt = 0; mt < 4; mt++) {
            int r0 = bm + wm * 64 + mt * 16 + g;
#pragma unroll
            for (int nt = 0; nt < 4; nt++) {
                int c0 = bn + wn * 32 + nt * 8 + tg * 2;
                float b0 = bias[c0], b1 = bias[c0 + 1];
                float2 v0 = make_float2(acc[mt][nt][0] + b0, acc[mt][nt][1] + b1);
                float2 v1 = make_float2(acc[mt][nt][2] + b0, acc[mt][nt][3] + b1);
                *(float2*)(C + (size_t)r0 * Nd + c0) = v0;
                *(float2*)(C + (size_t)(r0 + 8) * Nd + c0) = v1;
            }
        }
    } else {
        // scatter into q/k/v (B,12,N,64) head layout
#pragma unroll
        for (int nt = 0; nt < 4; nt++) {
            int c0 = bn + wn * 32 + nt * 8 + tg * 2;
            int t = c0 / Ddim;
            int rem = c0 - t * Ddim;
            int h = rem >> 6, d = rem & 63;
            float* dst = (t == 0) ? Qo : (t == 1) ? Ko : Vo;
#pragma unroll
            for (int mt = 0; mt < 4; mt++) {
                int r0 = bm + wm * 64 + mt * 16 + g;
#pragma unroll
                for (int rr = 0; rr < 2; rr++) {
                    int r = r0 + rr * 8;
                    int b = r / Ndim;
                    int n = r - b * Ndim;
                    size_t off = (((size_t)(b * Hh + h)) * Ndim + n) * HD + d;
                    float2 v = make_float2(acc[mt][nt][2 * rr], acc[mt][nt][2 * rr + 1]);
                    *(float2*)(dst + off) = v;
                }
            }
        }
    }
}

// ---------------------------------------------------------------------------
// fp32 -> bf16 hi/lo split
// ---------------------------------------------------------------------------
__global__ void cvt_split_k(const float* __restrict__ in,
                            __nv_bfloat16* __restrict__ hi,
                            __nv_bfloat16* __restrict__ lo, size_t n)
{
    size_t i = (size_t)blockIdx.x * 256 + threadIdx.x;
    if (i >= n) return;
    float v = in[i];
    __nv_bfloat16 h = __float2bfloat16(v);
    hi[i] = h;
    lo[i] = __float2bfloat16(v - __bfloat162float(h));
}

// ---------------------------------------------------------------------------
// Spatial attention (R7 version): 768 groups of 196 rows (heads 0..5).
// 224 threads (196 active). Writes g_wf_hi/lo head-interleaved + bf16 split.
// ---------------------------------------------------------------------------
#define SPAT_T 224
__global__ __launch_bounds__(SPAT_T) void attn_spatial_k()
{
    __shared__ float4 K4[64][16];
    __shared__ float4 V4[64][16];

    const int g = blockIdx.x;
    const int b = g / 96;
    const int h = (g % 96) / 16;
    const int f = g % 16;
    const size_t base = (((size_t)(b * Hh + h)) * Ndim + f * Pdim) * HD;

    const int tid = threadIdx.x;
    const bool active = tid < Pdim;

    float4 q4[16], a4[16];
    float mx = -1e30f, lsum = 0.f;
    if (active) {
        const float4* qp = (const float4*)(g_q + base + (size_t)tid * HD);
#pragma unroll
        for (int i = 0; i < 16; i++) q4[i] = qp[i];
#pragma unroll
        for (int i = 0; i < 16; i++) a4[i] = make_float4(0.f, 0.f, 0.f, 0.f);
    }

    const float scale = 0.125f;

    for (int j0 = 0; j0 < Pdim; j0 += 64) {
        int cnt = Pdim - j0; if (cnt > 64) cnt = 64;
        __syncthreads();
        {
            const float4* kp = (const float4*)(g_k + base + (size_t)j0 * HD);
            const float4* vp = (const float4*)(g_v + base + (size_t)j0 * HD);
            for (int t = tid; t < cnt * 16; t += SPAT_T) {
                K4[t >> 4][t & 15] = kp[t];
                V4[t >> 4][t & 15] = vp[t];
            }
        }
        __syncthreads();
        if (active) {
            for (int j = 0; j < cnt; j++) {
                float s = 0.f;
#pragma unroll
                for (int i = 0; i < 16; i++) {
                    float4 kv = K4[j][i];
                    s = fmaf(q4[i].x, kv.x, s);
                    s = fmaf(q4[i].y, kv.y, s);
                    s = fmaf(q4[i].z, kv.z, s);
                    s = fmaf(q4[i].w, kv.w, s);
                }
                s *= scale;
                if (s <= mx) {
                    float p = __expf(s - mx);
                    lsum += p;
#pragma unroll
                    for (int i = 0; i < 16; i++) {
                        float4 vv = V4[j][i];
                        a4[i].x = fmaf(p, vv.x, a4[i].x);
                        a4[i].y = fmaf(p, vv.y, a4[i].y);
                        a4[i].z = fmaf(p, vv.z, a4[i].z);
                        a4[i].w = fmaf(p, vv.w, a4[i].w);
                    }
                } else {
                    float corr = __expf(mx - s);
                    lsum = lsum * corr + 1.f;
#pragma unroll
                    for (int i = 0; i < 16; i++) {
                        float4 vv = V4[j][i];
                        a4[i].x = fmaf(a4[i].x, corr, vv.x);
                        a4[i].y = fmaf(a4[i].y, corr, vv.y);
                        a4[i].z = fmaf(a4[i].z, corr, vv.z);
                        a4[i].w = fmaf(a4[i].w, corr, vv.w);
                    }
                    mx = s;
                }
            }
        }
    }

    if (active) {
        float inv = 1.f / lsum;
        const int nglob = f * Pdim + tid;
        const size_t obase = ((size_t)b * Ndim + nglob) * Ddim + h * HD;
#pragma unroll
        for (int i = 0; i < 16; i++) {
            float vals[4] = { a4[i].x * inv, a4[i].y * inv, a4[i].z * inv, a4[i].w * inv };
#pragma unroll
            for (int j = 0; j < 4; j += 2) {
                float v0 = vals[j], v1 = vals[j + 1];
                __nv_bfloat16 h0 = __float2bfloat16(v0);
                __nv_bfloat16 h1 = __float2bfloat16(v1);
                __nv_bfloat162 hv; hv.x = h0; hv.y = h1;
                __nv_bfloat162 lv;
                lv.x = __float2bfloat16(v0 - __bfloat162float(h0));
                lv.y = __float2bfloat16(v1 - __bfloat162float(h1));
                *(__nv_bfloat162*)(g_wf_hi + obase + i * 4 + j) = hv;
                *(__nv_bfloat162*)(g_wf_lo + obase + i * 4 + j) = lv;
            }
        }
    }
}

// ---------------------------------------------------------------------------
// Temporal attention: heads 6..11, groups of 16 rows. Writes g_wf directly.
// ---------------------------------------------------------------------------
__global__ __launch_bounds__(128) void attn_temporal_k()
{
    int tid = blockIdx.x * 128 + threadIdx.x;
    const int TOT = Bdim * 6 * Ndim;
    if (tid >= TOT) return;
    int b = tid / (6 * Ndim);
    int rr = tid - b * (6 * Ndim);
    int h = 6 + rr / Ndim;
    int n = rr % Ndim;
    int n0 = n & ~15;
    size_t row = (((size_t)(b * Hh + h)) * Ndim + n) * HD;
    size_t gb  = (((size_t)(b * Hh + h)) * Ndim + n0) * HD;

    float4 q4[16];
    const float4* qp = (const float4*)(g_q + row);
#pragma unroll
    for (int i = 0; i < 16; i++) q4[i] = qp[i];

    float s[16];
    float mx = -1e30f;
#pragma unroll
    for (int f = 0; f < 16; f++) {
        const float4* kp = (const float4*)(g_k + gb + (size_t)f * HD);
        float a = 0.f;
#pragma unroll
        for (int i = 0; i < 16; i++) {
            float4 kv = kp[i];
            a = fmaf(q4[i].x, kv.x, a);
            a = fmaf(q4[i].y, kv.y, a);
            a = fmaf(q4[i].z, kv.z, a);
            a = fmaf(q4[i].w, kv.w, a);
        }
        s[f] = a * 0.125f;
        mx = fmaxf(mx, s[f]);
    }
    float lsum = 0.f;
#pragma unroll
    for (int f = 0; f < 16; f++) { s[f] = __expf(s[f] - mx); lsum += s[f]; }
    float inv = 1.f / lsum;
#pragma unroll
    for (int f = 0; f < 16; f++) s[f] *= inv;

    const size_t obase = ((size_t)b * Ndim + n) * Ddim + h * HD;
#pragma unroll
    for (int ch = 0; ch < 4; ch++) {
        float4 a4[4];
#pragma unroll
        for (int i = 0; i < 4; i++) a4[i] = make_float4(0.f, 0.f, 0.f, 0.f);
#pragma unroll
        for (int f = 0; f < 16; f++) {
            float p = s[f];
            const float4* vp = (const float4*)(g_v + gb + (size_t)f * HD + ch * 16);
#pragma unroll
            for (int i = 0; i < 4; i++) {
                float4 vv = vp[i];
                a4[i].x = fmaf(p, vv.x, a4[i].x);
                a4[i].y = fmaf(p, vv.y, a4[i].y);
                a4[i].z = fmaf(p, vv.z, a4[i].z);
                a4[i].w = fmaf(p, vv.w, a4[i].w);
            }
        }
#pragma unroll
        for (int i = 0; i < 4; i++) {
            float vals[4] = { a4[i].x, a4[i].y, a4[i].z, a4[i].w };
#pragma unroll
            for (int j = 0; j < 4; j += 2) {
                float v0 = vals[j], v1 = vals[j + 1];
                __nv_bfloat16 h0 = __float2bfloat16(v0);
                __nv_bfloat16 h1 = __float2bfloat16(v1);
                __nv_bfloat162 hv; hv.x = h0; hv.y = h1;
                __nv_bfloat162 lv;
                lv.x = __float2bfloat16(v0 - __bfloat162float(h0));
                lv.y = __float2bfloat16(v1 - __bfloat162float(h1));
                size_t o = obase + ch * 16 + i * 4 + j;
                *(__nv_bfloat162*)(g_wf_hi + o) = hv;
                *(__nv_bfloat162*)(g_wf_lo + o) = lv;
            }
        }
    }
}

// ---------------------------------------------------------------------------
// Launch
// ---------------------------------------------------------------------------
extern "C" void kernel_launch(void* const* d_in, const int* in_sizes, int n_in,
                              void* d_out, int out_size)
{
    const float* x      = (const float*)d_in[0];
    const float* w_qkv  = (const float*)d_in[1];
    const float* w_proj = (const float*)d_in[2];
    const float* b_proj = (const float*)d_in[3];
    float* out = (float*)d_out;

    float *p_q, *p_k, *p_v;
    __nv_bfloat16 *p_xhi, *p_xlo, *p_qkvw_hi, *p_qkvw_lo;
    __nv_bfloat16 *p_projw_hi, *p_projw_lo, *p_wfhi, *p_wflo;
    cudaGetSymbolAddress((void**)&p_q, g_q);
    cudaGetSymbolAddress((void**)&p_k, g_k);
    cudaGetSymbolAddress((void**)&p_v, g_v);
    cudaGetSymbolAddress((void**)&p_xhi, g_xhi);
    cudaGetSymbolAddress((void**)&p_xlo, g_xlo);
    cudaGetSymbolAddress((void**)&p_qkvw_hi, g_wqkv_hi);
    cudaGetSymbolAddress((void**)&p_qkvw_lo, g_wqkv_lo);
    cudaGetSymbolAddress((void**)&p_projw_hi, g_wproj_hi);
    cudaGetSymbolAddress((void**)&p_projw_lo, g_wproj_lo);
    cudaGetSymbolAddress((void**)&p_wfhi, g_wf_hi);
    cudaGetSymbolAddress((void**)&p_wflo, g_wf_lo);

    cudaFuncSetAttribute(tgemm_k, cudaFuncAttributeMaxDynamicSharedMemorySize, GSMEM);

    // 0) bf16 splits of inputs / weights
    cvt_split_k<<<(unsigned)((MD_ELEMS + 255) / 256), 256>>>(x, p_xhi, p_xlo, MD_ELEMS);
    cvt_split_k<<<(unsigned)(((size_t)E3 * Ddim + 255) / 256), 256>>>(
        w_qkv, p_qkvw_hi, p_qkvw_lo, (size_t)E3 * Ddim);
    cvt_split_k<<<(unsigned)(((size_t)Ddim * Ddim + 255) / 256), 256>>>(
        w_proj, p_projw_hi, p_projw_lo, (size_t)Ddim * Ddim);

    // 1) qkv GEMM with fused scatter into q/k/v head layout
    tgemm_k<<<dim3(E3 / 128, Mrows / 128), 256, GSMEM>>>(
        p_xhi, p_xlo, p_qkvw_hi, p_qkvw_lo, nullptr, nullptr, E3, 0,
        p_q, p_k, p_v);

    // 2) spatial attention (writes g_wf_hi/lo directly)
    attn_spatial_k<<<768, SPAT_T>>>();

    // 3) temporal attention (writes g_wf_hi/lo directly)
    attn_temporal_k<<<(Bdim * 6 * Ndim) / 128, 128>>>();

    // 4) out = wf @ w_proj^T + b_proj
    tgemm_k<<<dim3(Ddim / 128, Mrows / 128), 256, GSMEM>>>(
        p_wfhi, p_wflo, p_projw_hi, p_projw_lo, b_proj, out, Ddim, 1,
        nullptr, nullptr, nullptr);
}

// round 11
// speedup vs baseline: 1.3957x; 1.3957x over previous
#include <cuda_runtime.h>
#include <cuda_bf16.h>
#include <cstdint>
#include <cstddef>

// ---------------------------------------------------------------------------
// Problem constants
// ---------------------------------------------------------------------------
#define Bdim  8
#define Fdim  16
#define Pdim  196
#define Ddim  768
#define Hh    12
#define HD    64
#define Ndim  3136              // F*P
#define Mrows 25088             // B*N
#define E3    2304              // 3*D

#define HEAD_ELEMS ((size_t)Bdim * Hh * Ndim * HD)
#define MD_ELEMS   ((size_t)Mrows * Ddim)

// Scratch (__device__ globals; allocation-free rule)
__device__ float g_q[HEAD_ELEMS];
__device__ float g_k[HEAD_ELEMS];
__device__ float g_v[HEAD_ELEMS];

__device__ __nv_bfloat16 g_xhi[MD_ELEMS];
__device__ __nv_bfloat16 g_xlo[MD_ELEMS];
__device__ __nv_bfloat16 g_wqkv_hi[(size_t)E3 * Ddim];
__device__ __nv_bfloat16 g_wqkv_lo[(size_t)E3 * Ddim];
__device__ __nv_bfloat16 g_wproj_hi[(size_t)Ddim * Ddim];
__device__ __nv_bfloat16 g_wproj_lo[(size_t)Ddim * Ddim];
__device__ __nv_bfloat16 g_wf_hi[MD_ELEMS];
__device__ __nv_bfloat16 g_wf_lo[MD_ELEMS];

// ---------------------------------------------------------------------------
// helpers
// ---------------------------------------------------------------------------
__device__ __forceinline__ void cp_async16(uint32_t dst, const void* src) {
    asm volatile("cp.async.cg.shared.global [%0], [%1], 16;"
                 :: "r"(dst), "l"(src) : "memory");
}
#define CP_COMMIT() asm volatile("cp.async.commit_group;" ::: "memory")
template <int N> __device__ __forceinline__ void cp_wait() {
    asm volatile("cp.async.wait_group %0;" :: "n"(N) : "memory");
}
__device__ __forceinline__ uint32_t smem_u32(const void* p) {
    uint32_t a;
    asm("{ .reg .u64 t; cvta.to.shared.u64 t, %1; cvt.u32.u64 %0, t; }"
        : "=r"(a) : "l"(p));
    return a;
}

__device__ __forceinline__ void mma16816(float* d,
                                         uint32_t a0, uint32_t a1, uint32_t a2, uint32_t a3,
                                         uint32_t b0, uint32_t b1) {
    asm volatile(
        "mma.sync.aligned.m16n8k16.row.col.f32.bf16.bf16.f32 "
        "{%0,%1,%2,%3}, {%4,%5,%6,%7}, {%8,%9}, {%0,%1,%2,%3};"
        : "+f"(d[0]), "+f"(d[1]), "+f"(d[2]), "+f"(d[3])
        : "r"(a0), "r"(a1), "r"(a2), "r"(a3), "r"(b0), "r"(b1));
}

__device__ __forceinline__ void ldsm4(uint32_t& r0, uint32_t& r1,
                                      uint32_t& r2, uint32_t& r3, uint32_t addr) {
    asm volatile("ldmatrix.sync.aligned.m8n8.x4.shared.b16 {%0,%1,%2,%3}, [%4];"
                 : "=r"(r0), "=r"(r1), "=r"(r2), "=r"(r3) : "r"(addr));
}

__device__ __forceinline__ uint32_t pack_bf16x2(float x, float y) {
    __nv_bfloat162 t = __floats2bfloat162_rn(x, y);
    return *(uint32_t*)&t;
}

// ---------------------------------------------------------------------------
// HMMA GEMM (R7 config):  C = (Ahi+Alo)[M,768] * (Bhi+Blo)[N,768]^T
// 128x128x32 CTA tile, 256 threads, warp grid 2(M)x4(N), warp tile 64x32.
// LDK=40 (80B rows, conflict-free ldmatrix), 2-stage cp.async, single sync.
// mode 0: scatter epilogue into q/k/v head layout; mode 1: C + bias.
// ---------------------------------------------------------------------------
#define BK       32
#define LDK      40
#define TILE_B   (128 * LDK * 2)          // 10240
#define STAGE_B  (4 * TILE_B)             // 40960
#define GSMEM    (2 * STAGE_B)            // 81920
#define OFF_AHI  0
#define OFF_ALO  TILE_B
#define OFF_BHI  (2 * TILE_B)
#define OFF_BLO  (3 * TILE_B)

__global__ __launch_bounds__(256, 2) void tgemm_k(
    const __nv_bfloat16* __restrict__ Ahi, const __nv_bfloat16* __restrict__ Alo,
    const __nv_bfloat16* __restrict__ Bhi, const __nv_bfloat16* __restrict__ Blo,
    const float* __restrict__ bias, float* __restrict__ C, int Nd, int mode,
    float* __restrict__ Qo, float* __restrict__ Ko, float* __restrict__ Vo)
{
    extern __shared__ char smem[];
    const uint32_t sb = smem_u32(smem);

    const int tid  = threadIdx.x;
    const int lane = tid & 31;
    const int wid  = tid >> 5;
    const int wm   = wid & 1;
    const int wn   = wid >> 1;
    const int g    = lane >> 2;
    const int tg   = lane & 3;

    const int bm = blockIdx.y * 128;
    const int bn = blockIdx.x * 128;

    const int a_row = wm * 64 + (lane & 15);
    const int a_kc  = (lane >> 4) * 8;
    const int b_row = wn * 32 + ((lane >> 4) << 3) + (lane & 7);
    const int b_kc  = ((lane >> 3) & 1) * 8;

    const int tile = tid >> 6;
    const int lt   = tid & 63;
    const __nv_bfloat16* src_base =
        (tile == 0) ? Ahi : (tile == 1) ? Alo : (tile == 2) ? Bhi : Blo;
    const int rowbase = (tile < 2) ? bm : bn;
    const uint32_t tile_off = tile * TILE_B;

    auto load_chunk = [&](int k0, int stage) {
        const uint32_t dbase = sb + stage * STAGE_B + tile_off;
#pragma unroll
        for (int j = 0; j < 8; j++) {
            int id  = lt + j * 64;
            int row = id >> 2;
            int gr  = id & 3;
            const void* src = src_base + (size_t)(rowbase + row) * Ddim + k0 + gr * 8;
            cp_async16(dbase + (uint32_t)(row * (LDK * 2) + gr * 16), src);
        }
        CP_COMMIT();
    };

    float acc[4][4][4];
#pragma unroll
    for (int i = 0; i < 4; i++)
#pragma unroll
        for (int j = 0; j < 4; j++)
#pragma unroll
            for (int q = 0; q < 4; q++) acc[i][j][q] = 0.f;

    load_chunk(0, 0);

    const int NCH = Ddim / BK;   // 24
    for (int c = 0; c < NCH; c++) {
        cp_wait<0>();
        __syncthreads();
        if (c + 1 < NCH) load_chunk((c + 1) * BK, (c + 1) & 1);

        const uint32_t st = sb + (c & 1) * STAGE_B;

#pragma unroll
        for (int ks = 0; ks < 2; ks++) {
            const int kcA = ks * 16 + a_kc;
            const int kcB = ks * 16 + b_kc;
            uint32_t ah[4][4], al[4][4];
#pragma unroll
            for (int mt = 0; mt < 4; mt++) {
                uint32_t addr = st + (uint32_t)(((a_row + mt * 16) * LDK + kcA) * 2);
                ldsm4(ah[mt][0], ah[mt][1], ah[mt][2], ah[mt][3], addr + OFF_AHI);
                ldsm4(al[mt][0], al[mt][1], al[mt][2], al[mt][3], addr + OFF_ALO);
            }
#pragma unroll
            for (int p = 0; p < 2; p++) {
                uint32_t baddr = st + (uint32_t)(((b_row + p * 16) * LDK + kcB) * 2);
                uint32_t bh[2][2], bl[2][2];
                ldsm4(bh[0][0], bh[0][1], bh[1][0], bh[1][1], baddr + OFF_BHI);
                ldsm4(bl[0][0], bl[0][1], bl[1][0], bl[1][1], baddr + OFF_BLO);
#pragma unroll
                for (int q = 0; q < 2; q++) {
                    const int nt = p * 2 + q;
#pragma unroll
                    for (int mt = 0; mt < 4; mt++) {
                        mma16816(acc[mt][nt], ah[mt][0], ah[mt][1], ah[mt][2], ah[mt][3],
                                 bh[q][0], bh[q][1]);
                        mma16816(acc[mt][nt], ah[mt][0], ah[mt][1], ah[mt][2], ah[mt][3],
                                 bl[q][0], bl[q][1]);
                        mma16816(acc[mt][nt], al[mt][0], al[mt][1], al[mt][2], al[mt][3],
                                 bh[q][0], bh[q][1]);
                    }
                }
            }
        }
    }

    if (mode == 1) {
#pragma unroll
        for (int mt = 0; mt < 4; mt++) {
            int r0 = bm + wm * 64 + mt * 16 + g;
#pragma unroll
            for (int nt = 0; nt < 4; nt++) {
                int c0 = bn + wn * 32 + nt * 8 + tg * 2;
                float b0 = bias[c0], b1 = bias[c0 + 1];
                float2 v0 = make_float2(acc[mt][nt][0] + b0, acc[mt][nt][1] + b1);
                float2 v1 = make_float2(acc[mt][nt][2] + b0, acc[mt][nt][3] + b1);
                *(float2*)(C + (size_t)r0 * Nd + c0) = v0;
                *(float2*)(C + (size_t)(r0 + 8) * Nd + c0) = v1;
            }
        }
    } else {
#pragma unroll
        for (int nt = 0; nt < 4; nt++) {
            int c0 = bn + wn * 32 + nt * 8 + tg * 2;
            int t = c0 / Ddim;
            int rem = c0 - t * Ddim;
            int h = rem >> 6, d = rem & 63;
            float* dst = (t == 0) ? Qo : (t == 1) ? Ko : Vo;
#pragma unroll
            for (int mt = 0; mt < 4; mt++) {
                int r0 = bm + wm * 64 + mt * 16 + g;
#pragma unroll
                for (int rr = 0; rr < 2; rr++) {
                    int r = r0 + rr * 8;
                    int b = r / Ndim;
                    int n = r - b * Ndim;
                    size_t off = (((size_t)(b * Hh + h)) * Ndim + n) * HD + d;
                    float2 v = make_float2(acc[mt][nt][2 * rr], acc[mt][nt][2 * rr + 1]);
                    *(float2*)(dst + off) = v;
                }
            }
        }
    }
}

// ---------------------------------------------------------------------------
// fp32 -> bf16 hi/lo split
// ---------------------------------------------------------------------------
__global__ void cvt_split_k(const float* __restrict__ in,
                            __nv_bfloat16* __restrict__ hi,
                            __nv_bfloat16* __restrict__ lo, size_t n)
{
    size_t i = (size_t)blockIdx.x * 256 + threadIdx.x;
    if (i >= n) return;
    float v = in[i];
    __nv_bfloat16 h = __float2bfloat16(v);
    hi[i] = h;
    lo[i] = __float2bfloat16(v - __bfloat162float(h));
}

// ---------------------------------------------------------------------------
// MMA flash spatial attention: 768 groups (heads 0..5), 196 q x 196 k, d=64.
// 13 warps (416 thr); warp = one 16-row m-tile (208-padded). Flash loop over
// 4 key chunks of 64. S and PV via bf16-split HMMA (hi*hi+hi*lo+lo*hi, fp32
// acc). V stored transposed in smem so PV B-operand matches tgemm's layout.
// Output -> g_wf_hi/lo (head-interleaved, bf16-split).
// ---------------------------------------------------------------------------
#define AT_T    416
#define MPAD    208
#define LDA     72                        // padded row (bf16), 144B stride
#define OQH     0
#define OQL     (MPAD * LDA * 2)          // 29952
#define OKH     (2 * MPAD * LDA * 2)      // 59904
#define OKL     (OKH + 64 * LDA * 2)      // 69120
#define OVH     (OKL + 64 * LDA * 2)      // 78336
#define OVL     (OVH + 64 * LDA * 2)      // 87552
#define ATSMEM  (OVL + 64 * LDA * 2)      // 96768

__global__ __launch_bounds__(AT_T, 1) void attn_spatial_k()
{
    extern __shared__ char smem[];
    const uint32_t sb = smem_u32(smem);
    __nv_bfloat16* Qhi = (__nv_bfloat16*)(smem + OQH);
    __nv_bfloat16* Qlo = (__nv_bfloat16*)(smem + OQL);
    __nv_bfloat16* Khi = (__nv_bfloat16*)(smem + OKH);
    __nv_bfloat16* Klo = (__nv_bfloat16*)(smem + OKL);
    __nv_bfloat16* Vth = (__nv_bfloat16*)(smem + OVH);
    __nv_bfloat16* Vtl = (__nv_bfloat16*)(smem + OVL);

    const int grp = blockIdx.x;
    const int b = grp / 96;
    const int h = (grp % 96) / 16;
    const int f = grp % 16;
    const size_t base = (((size_t)(b * Hh + h)) * Ndim + f * Pdim) * HD;

    const int tid  = threadIdx.x;
    const int lane = tid & 31;
    const int wid  = tid >> 5;          // m-tile 0..12
    const int gq   = lane >> 2;
    const int tg   = lane & 3;

    // fill Q (zero-pad rows >= 196)
    for (int idx = tid; idx < MPAD * 64; idx += AT_T) {
        int r = idx >> 6, c = idx & 63;
        float v = (r < Pdim) ? g_q[base + (size_t)r * HD + c] : 0.f;
        __nv_bfloat16 hv = __float2bfloat16(v);
        Qhi[r * LDA + c] = hv;
        Qlo[r * LDA + c] = __float2bfloat16(v - __bfloat162float(hv));
    }
    __syncthreads();

    // Q fragments (A-operand), loaded once
    uint32_t qh[4][4], ql[4][4];
    {
        const int arow = wid * 16 + (lane & 15);
        const int acol = (lane >> 4) * 8;
#pragma unroll
        for (int kb = 0; kb < 4; kb++) {
            uint32_t addr = sb + (uint32_t)((arow * LDA + kb * 16 + acol) * 2);
            ldsm4(qh[kb][0], qh[kb][1], qh[kb][2], qh[kb][3], addr + OQH);
            ldsm4(ql[kb][0], ql[kb][1], ql[kb][2], ql[kb][3], addr + OQL);
        }
    }

    float ofr[8][4];
#pragma unroll
    for (int j = 0; j < 8; j++)
#pragma unroll
        for (int q = 0; q < 4; q++) ofr[j][q] = 0.f;
    float mx0 = -1e30f, mx1 = -1e30f, ls0 = 0.f, ls1 = 0.f;
    const float scale = 0.125f;

    const int brow = ((lane >> 4) << 3) + (lane & 7);
    const int bcol = ((lane >> 3) & 1) * 8;

    for (int ch = 0; ch < 4; ch++) {
        __syncthreads();
        // fill K (row-major) and V transposed; zero invalid keys
        const int kbase = ch * 64;
        for (int idx = tid; idx < 64 * 64; idx += AT_T) {
            int r = idx >> 6, c = idx & 63;
            int key = kbase + r;
            float kv = (key < Pdim) ? g_k[base + (size_t)key * HD + c] : 0.f;
            __nv_bfloat16 khv = __float2bfloat16(kv);
            Khi[r * LDA + c] = khv;
            Klo[r * LDA + c] = __float2bfloat16(kv - __bfloat162float(khv));
            float vv = (key < Pdim) ? g_v[base + (size_t)key * HD + c] : 0.f;
            __nv_bfloat16 vhv = __float2bfloat16(vv);
            Vth[c * LDA + r] = vhv;
            Vtl[c * LDA + r] = __float2bfloat16(vv - __bfloat162float(vhv));
        }
        __syncthreads();

        // S = Q K^T (split)
        float sfr[8][4];
#pragma unroll
        for (int j = 0; j < 8; j++)
#pragma unroll
            for (int q = 0; q < 4; q++) sfr[j][q] = 0.f;

#pragma unroll
        for (int kb = 0; kb < 4; kb++) {
#pragma unroll
            for (int p = 0; p < 4; p++) {
                uint32_t ka = sb + (uint32_t)(((p * 16 + brow) * LDA + kb * 16 + bcol) * 2);
                uint32_t bh0, bh1, bh2, bh3, bl0, bl1, bl2, bl3;
                ldsm4(bh0, bh1, bh2, bh3, ka + OKH);
                ldsm4(bl0, bl1, bl2, bl3, ka + OKL);
                mma16816(sfr[2 * p], qh[kb][0], qh[kb][1], qh[kb][2], qh[kb][3], bh0, bh1);
                mma16816(sfr[2 * p], qh[kb][0], qh[kb][1], qh[kb][2], qh[kb][3], bl0, bl1);
                mma16816(sfr[2 * p], ql[kb][0], ql[kb][1], ql[kb][2], ql[kb][3], bh0, bh1);
                mma16816(sfr[2 * p + 1], qh[kb][0], qh[kb][1], qh[kb][2], qh[kb][3], bh2, bh3);
                mma16816(sfr[2 * p + 1], qh[kb][0], qh[kb][1], qh[kb][2], qh[kb][3], bl2, bl3);
                mma16816(sfr[2 * p + 1], ql[kb][0], ql[kb][1], ql[kb][2], ql[kb][3], bh2, bh3);
            }
        }

        // scale + mask invalid keys
        const int nvalid = Pdim - kbase;     // 64,64,64,4
#pragma unroll
        for (int j = 0; j < 8; j++)
#pragma unroll
            for (int q = 0; q < 4; q++) {
                int key = j * 8 + 2 * tg + (q & 1);
                sfr[j][q] = (key < nvalid) ? sfr[j][q] * scale : -1e30f;
            }

        // online softmax update
        float rm0 = -1e30f, rm1 = -1e30f;
#pragma unroll
        for (int j = 0; j < 8; j++) {
            rm0 = fmaxf(rm0, fmaxf(sfr[j][0], sfr[j][1]));
            rm1 = fmaxf(rm1, fmaxf(sfr[j][2], sfr[j][3]));
        }
        rm0 = fmaxf(rm0, __shfl_xor_sync(0xFFFFFFFFu, rm0, 1));
        rm0 = fmaxf(rm0, __shfl_xor_sync(0xFFFFFFFFu, rm0, 2));
        rm1 = fmaxf(rm1, __shfl_xor_sync(0xFFFFFFFFu, rm1, 1));
        rm1 = fmaxf(rm1, __shfl_xor_sync(0xFFFFFFFFu, rm1, 2));
        float nm0 = fmaxf(mx0, rm0), nm1 = fmaxf(mx1, rm1);
        float c0 = __expf(mx0 - nm0), c1 = __expf(mx1 - nm1);
        mx0 = nm0; mx1 = nm1;
        ls0 *= c0; ls1 *= c1;
#pragma unroll
        for (int j = 0; j < 8; j++) {
            ofr[j][0] *= c0; ofr[j][1] *= c0;
            ofr[j][2] *= c1; ofr[j][3] *= c1;
        }

        // p = exp(s - m), row sums; overwrite sfr with p
        float rs0 = 0.f, rs1 = 0.f;
#pragma unroll
        for (int j = 0; j < 8; j++) {
            float p0 = __expf(sfr[j][0] - nm0);
            float p1 = __expf(sfr[j][1] - nm0);
            float p2 = __expf(sfr[j][2] - nm1);
            float p3 = __expf(sfr[j][3] - nm1);
            rs0 += p0 + p1; rs1 += p2 + p3;
            sfr[j][0] = p0; sfr[j][1] = p1; sfr[j][2] = p2; sfr[j][3] = p3;
        }
        rs0 += __shfl_xor_sync(0xFFFFFFFFu, rs0, 1);
        rs0 += __shfl_xor_sync(0xFFFFFFFFu, rs0, 2);
        rs1 += __shfl_xor_sync(0xFFFFFFFFu, rs1, 1);
        rs1 += __shfl_xor_sync(0xFFFFFFFFu, rs1, 2);
        ls0 += rs0; ls1 += rs1;

        // PV: per k16-block, pack P (hi/lo) then accumulate into O
#pragma unroll
        for (int kb = 0; kb < 4; kb++) {
            uint32_t pah[4], pal[4];
#pragma unroll
            for (int half = 0; half < 2; half++) {
                const int j = 2 * kb + half;
                float p0 = sfr[j][0], p1 = sfr[j][1], p2 = sfr[j][2], p3 = sfr[j][3];
                __nv_bfloat16 h0 = __float2bfloat16(p0);
                __nv_bfloat16 h1 = __float2bfloat16(p1);
                __nv_bfloat16 h2 = __float2bfloat16(p2);
                __nv_bfloat16 h3 = __float2bfloat16(p3);
                pah[2 * half + 0] = pack_bf16x2(__bfloat162float(h0), __bfloat162float(h1));
                pah[2 * half + 1] = pack_bf16x2(__bfloat162float(h2), __bfloat162float(h3));
                pal[2 * half + 0] = pack_bf16x2(p0 - __bfloat162float(h0), p1 - __bfloat162float(h1));
                pal[2 * half + 1] = pack_bf16x2(p2 - __bfloat162float(h2), p3 - __bfloat162float(h3));
            }
            // note: pah index order must be a0,a1,a2,a3 = (j even c01),(j even c23),(j odd c01),(j odd c23)
#pragma unroll
            for (int p = 0; p < 4; p++) {
                uint32_t va = sb + (uint32_t)(((p * 16 + brow) * LDA + kb * 16 + bcol) * 2);
                uint32_t vh0, vh1, vh2, vh3, vl0, vl1, vl2, vl3;
                ldsm4(vh0, vh1, vh2, vh3, va + OVH);
                ldsm4(vl0, vl1, vl2, vl3, va + OVL);
                mma16816(ofr[2 * p], pah[0], pah[1], pah[2], pah[3], vh0, vh1);
                mma16816(ofr[2 * p], pah[0], pah[1], pah[2], pah[3], vl0, vl1);
                mma16816(ofr[2 * p], pal[0], pal[1], pal[2], pal[3], vh0, vh1);
                mma16816(ofr[2 * p + 1], pah[0], pah[1], pah[2], pah[3], vh2, vh3);
                mma16816(ofr[2 * p + 1], pah[0], pah[1], pah[2], pah[3], vl2, vl3);
                mma16816(ofr[2 * p + 1], pal[0], pal[1], pal[2], pal[3], vh2, vh3);
            }
        }
    }

    // epilogue: normalize, bf16-split, store head-interleaved
    float inv0 = 1.f / ls0, inv1 = 1.f / ls1;
    const int r0 = wid * 16 + gq;
    const int r1 = r0 + 8;
    if (r0 < Pdim) {
        const size_t ob = ((size_t)b * Ndim + (f * Pdim + r0)) * Ddim + h * HD;
#pragma unroll
        for (int j = 0; j < 8; j++) {
            float v0 = ofr[j][0] * inv0, v1 = ofr[j][1] * inv0;
            __nv_bfloat16 h0 = __float2bfloat16(v0);
            __nv_bfloat16 h1 = __float2bfloat16(v1);
            __nv_bfloat162 hv; hv.x = h0; hv.y = h1;
            __nv_bfloat162 lv;
            lv.x = __float2bfloat16(v0 - __bfloat162float(h0));
            lv.y = __float2bfloat16(v1 - __bfloat162float(h1));
            *(__nv_bfloat162*)(g_wf_hi + ob + j * 8 + 2 * tg) = hv;
            *(__nv_bfloat162*)(g_wf_lo + ob + j * 8 + 2 * tg) = lv;
        }
    }
    if (r1 < Pdim) {
        const size_t ob = ((size_t)b * Ndim + (f * Pdim + r1)) * Ddim + h * HD;
#pragma unroll
        for (int j = 0; j < 8; j++) {
            float v0 = ofr[j][2] * inv1, v1 = ofr[j][3] * inv1;
            __nv_bfloat16 h0 = __float2bfloat16(v0);
            __nv_bfloat16 h1 = __float2bfloat16(v1);
            __nv_bfloat162 hv; hv.x = h0; hv.y = h1;
            __nv_bfloat162 lv;
            lv.x = __float2bfloat16(v0 - __bfloat162float(h0));
            lv.y = __float2bfloat16(v1 - __bfloat162float(h1));
            *(__nv_bfloat162*)(g_wf_hi + ob + j * 8 + 2 * tg) = hv;
            *(__nv_bfloat162*)(g_wf_lo + ob + j * 8 + 2 * tg) = lv;
        }
    }
}

// ---------------------------------------------------------------------------
// Temporal attention: heads 6..11, groups of 16 rows. Writes g_wf directly.
// ---------------------------------------------------------------------------
__global__ __launch_bounds__(128) void attn_temporal_k()
{
    int tid = blockIdx.x * 128 + threadIdx.x;
    const int TOT = Bdim * 6 * Ndim;
    if (tid >= TOT) return;
    int b = tid / (6 * Ndim);
    int rr = tid - b * (6 * Ndim);
    int h = 6 + rr / Ndim;
    int n = rr % Ndim;
    int n0 = n & ~15;
    size_t row = (((size_t)(b * Hh + h)) * Ndim + n) * HD;
    size_t gb  = (((size_t)(b * Hh + h)) * Ndim + n0) * HD;

    float4 q4[16];
    const float4* qp = (const float4*)(g_q + row);
#pragma unroll
    for (int i = 0; i < 16; i++) q4[i] = qp[i];

    float s[16];
    float mx = -1e30f;
#pragma unroll
    for (int f = 0; f < 16; f++) {
        const float4* kp = (const float4*)(g_k + gb + (size_t)f * HD);
        float a = 0.f;
#pragma unroll
        for (int i = 0; i < 16; i++) {
            float4 kv = kp[i];
            a = fmaf(q4[i].x, kv.x, a);
            a = fmaf(q4[i].y, kv.y, a);
            a = fmaf(q4[i].z, kv.z, a);
            a = fmaf(q4[i].w, kv.w, a);
        }
        s[f] = a * 0.125f;
        mx = fmaxf(mx, s[f]);
    }
    float lsum = 0.f;
#pragma unroll
    for (int f = 0; f < 16; f++) { s[f] = __expf(s[f] - mx); lsum += s[f]; }
    float inv = 1.f / lsum;
#pragma unroll
    for (int f = 0; f < 16; f++) s[f] *= inv;

    const size_t obase = ((size_t)b * Ndim + n) * Ddim + h * HD;
#pragma unroll
    for (int ch = 0; ch < 4; ch++) {
        float4 a4[4];
#pragma unroll
        for (int i = 0; i < 4; i++) a4[i] = make_float4(0.f, 0.f, 0.f, 0.f);
#pragma unroll
        for (int f = 0; f < 16; f++) {
            float p = s[f];
            const float4* vp = (const float4*)(g_v + gb + (size_t)f * HD + ch * 16);
#pragma unroll
            for (int i = 0; i < 4; i++) {
                float4 vv = vp[i];
                a4[i].x = fmaf(p, vv.x, a4[i].x);
                a4[i].y = fmaf(p, vv.y, a4[i].y);
                a4[i].z = fmaf(p, vv.z, a4[i].z);
                a4[i].w = fmaf(p, vv.w, a4[i].w);
            }
        }
#pragma unroll
        for (int i = 0; i < 4; i++) {
            float vals[4] = { a4[i].x, a4[i].y, a4[i].z, a4[i].w };
#pragma unroll
            for (int j = 0; j < 4; j += 2) {
                float v0 = vals[j], v1 = vals[j + 1];
                __nv_bfloat16 h0 = __float2bfloat16(v0);
                __nv_bfloat16 h1 = __float2bfloat16(v1);
                __nv_bfloat162 hv; hv.x = h0; hv.y = h1;
                __nv_bfloat162 lv;
                lv.x = __float2bfloat16(v0 - __bfloat162float(h0));
                lv.y = __float2bfloat16(v1 - __bfloat162float(h1));
                size_t o = obase + ch * 16 + i * 4 + j;
                *(__nv_bfloat162*)(g_wf_hi + o) = hv;
                *(__nv_bfloat162*)(g_wf_lo + o) = lv;
            }
        }
    }
}

// ---------------------------------------------------------------------------
// Launch
// ---------------------------------------------------------------------------
extern "C" void kernel_launch(void* const* d_in, const int* in_sizes, int n_in,
                              void* d_out, int out_size)
{
    const float* x      = (const float*)d_in[0];
    const float* w_qkv  = (const float*)d_in[1];
    const float* w_proj = (const float*)d_in[2];
    const float* b_proj = (const float*)d_in[3];
    float* out = (float*)d_out;

    float *p_q, *p_k, *p_v;
    __nv_bfloat16 *p_xhi, *p_xlo, *p_qkvw_hi, *p_qkvw_lo;
    __nv_bfloat16 *p_projw_hi, *p_projw_lo, *p_wfhi, *p_wflo;
    cudaGetSymbolAddress((void**)&p_q, g_q);
    cudaGetSymbolAddress((void**)&p_k, g_k);
    cudaGetSymbolAddress((void**)&p_v, g_v);
    cudaGetSymbolAddress((void**)&p_xhi, g_xhi);
    cudaGetSymbolAddress((void**)&p_xlo, g_xlo);
    cudaGetSymbolAddress((void**)&p_qkvw_hi, g_wqkv_hi);
    cudaGetSymbolAddress((void**)&p_qkvw_lo, g_wqkv_lo);
    cudaGetSymbolAddress((void**)&p_projw_hi, g_wproj_hi);
    cudaGetSymbolAddress((void**)&p_projw_lo, g_wproj_lo);
    cudaGetSymbolAddress((void**)&p_wfhi, g_wf_hi);
    cudaGetSymbolAddress((void**)&p_wflo, g_wf_lo);

    cudaFuncSetAttribute(tgemm_k, cudaFuncAttributeMaxDynamicSharedMemorySize, GSMEM);
    cudaFuncSetAttribute(attn_spatial_k, cudaFuncAttributeMaxDynamicSharedMemorySize, ATSMEM);

    // 0) bf16 splits of inputs / weights
    cvt_split_k<<<(unsigned)((MD_ELEMS + 255) / 256), 256>>>(x, p_xhi, p_xlo, MD_ELEMS);
    cvt_split_k<<<(unsigned)(((size_t)E3 * Ddim + 255) / 256), 256>>>(
        w_qkv, p_qkvw_hi, p_qkvw_lo, (size_t)E3 * Ddim);
    cvt_split_k<<<(unsigned)(((size_t)Ddim * Ddim + 255) / 256), 256>>>(
        w_proj, p_projw_hi, p_projw_lo, (size_t)Ddim * Ddim);

    // 1) qkv GEMM with fused scatter into q/k/v head layout
    tgemm_k<<<dim3(E3 / 128, Mrows / 128), 256, GSMEM>>>(
        p_xhi, p_xlo, p_qkvw_hi, p_qkvw_lo, nullptr, nullptr, E3, 0,
        p_q, p_k, p_v);

    // 2) MMA flash spatial attention
    attn_spatial_k<<<768, AT_T, ATSMEM>>>();

    // 3) temporal attention
    attn_temporal_k<<<(Bdim * 6 * Ndim) / 128, 128>>>();

    // 4) out = wf @ w_proj^T + b_proj
    tgemm_k<<<dim3(Ddim / 128, Mrows / 128), 256, GSMEM>>>(
        p_wfhi, p_wflo, p_projw_hi, p_projw_lo, b_proj, out, Ddim, 1,
        nullptr, nullptr, nullptr);
}

// round 12
// speedup vs baseline: 1.7285x; 1.2384x over previous
#include <cuda_runtime.h>
#include <cuda_bf16.h>
#include <cuda_fp16.h>
#include <cstdint>
#include <cstddef>

// ---------------------------------------------------------------------------
// Problem constants
// ---------------------------------------------------------------------------
#define Bdim  8
#define Fdim  16
#define Pdim  196
#define Ddim  768
#define Hh    12
#define HD    64
#define Ndim  3136              // F*P
#define Mrows 25088             // B*N
#define E3    2304              // 3*D

#define HEAD_ELEMS ((size_t)Bdim * Hh * Ndim * HD)
#define MD_ELEMS   ((size_t)Mrows * Ddim)

// Scratch (__device__ globals; allocation-free rule)
__device__ float g_q[HEAD_ELEMS];
__device__ float g_k[HEAD_ELEMS];
__device__ float g_v[HEAD_ELEMS];

__device__ __half g_xhi[MD_ELEMS];
__device__ __half g_xlo[MD_ELEMS];
__device__ __half g_wqkv[(size_t)E3 * Ddim];
__device__ __half g_wproj[(size_t)Ddim * Ddim];
__device__ __half g_wf_hi[MD_ELEMS];
__device__ __half g_wf_lo[MD_ELEMS];

// ---------------------------------------------------------------------------
// helpers
// ---------------------------------------------------------------------------
__device__ __forceinline__ void cp_async16(uint32_t dst, const void* src) {
    asm volatile("cp.async.cg.shared.global [%0], [%1], 16;"
                 :: "r"(dst), "l"(src) : "memory");
}
#define CP_COMMIT() asm volatile("cp.async.commit_group;" ::: "memory")
template <int N> __device__ __forceinline__ void cp_wait() {
    asm volatile("cp.async.wait_group %0;" :: "n"(N) : "memory");
}
__device__ __forceinline__ uint32_t smem_u32(const void* p) {
    uint32_t a;
    asm("{ .reg .u64 t; cvta.to.shared.u64 t, %1; cvt.u32.u64 %0, t; }"
        : "=r"(a) : "l"(p));
    return a;
}

// bf16 mma (attention)
__device__ __forceinline__ void mma16816(float* d,
                                         uint32_t a0, uint32_t a1, uint32_t a2, uint32_t a3,
                                         uint32_t b0, uint32_t b1) {
    asm volatile(
        "mma.sync.aligned.m16n8k16.row.col.f32.bf16.bf16.f32 "
        "{%0,%1,%2,%3}, {%4,%5,%6,%7}, {%8,%9}, {%0,%1,%2,%3};"
        : "+f"(d[0]), "+f"(d[1]), "+f"(d[2]), "+f"(d[3])
        : "r"(a0), "r"(a1), "r"(a2), "r"(a3), "r"(b0), "r"(b1));
}
// fp16 mma (GEMMs)
__device__ __forceinline__ void mma16816h(float* d,
                                          uint32_t a0, uint32_t a1, uint32_t a2, uint32_t a3,
                                          uint32_t b0, uint32_t b1) {
    asm volatile(
        "mma.sync.aligned.m16n8k16.row.col.f32.f16.f16.f32 "
        "{%0,%1,%2,%3}, {%4,%5,%6,%7}, {%8,%9}, {%0,%1,%2,%3};"
        : "+f"(d[0]), "+f"(d[1]), "+f"(d[2]), "+f"(d[3])
        : "r"(a0), "r"(a1), "r"(a2), "r"(a3), "r"(b0), "r"(b1));
}

__device__ __forceinline__ void ldsm4(uint32_t& r0, uint32_t& r1,
                                      uint32_t& r2, uint32_t& r3, uint32_t addr) {
    asm volatile("ldmatrix.sync.aligned.m8n8.x4.shared.b16 {%0,%1,%2,%3}, [%4];"
                 : "=r"(r0), "=r"(r1), "=r"(r2), "=r"(r3) : "r"(addr));
}

__device__ __forceinline__ uint32_t pack_bf16x2(float x, float y) {
    __nv_bfloat162 t = __floats2bfloat162_rn(x, y);
    return *(uint32_t*)&t;
}

// ---------------------------------------------------------------------------
// HMMA GEMM (fp16, 2-pass):  C = (Ahi+Alo)[M,768] * B[N,768]^T
// A split fp16 hi/lo; B single fp16 (2^-11 rounding, norm-error ~3e-4).
// 128x128x32 CTA tile, 256 threads, warp grid 2(M)x4(N), warp tile 64x32.
// LDK=40 (80B rows, conflict-free ldmatrix), 2-stage cp.async, single sync.
// mode 0: scatter epilogue into q/k/v head layout; mode 1: C + bias.
// ---------------------------------------------------------------------------
#define BK       32
#define LDK      40
#define TILE_B   (128 * LDK * 2)          // 10240
#define STAGE_B  (3 * TILE_B)             // 30720 (Ahi, Alo, B)
#define GSMEM    (2 * STAGE_B)            // 61440
#define OFF_AHI  0
#define OFF_ALO  TILE_B
#define OFF_B    (2 * TILE_B)

__global__ __launch_bounds__(256, 2) void tgemm_k(
    const __half* __restrict__ Ahi, const __half* __restrict__ Alo,
    const __half* __restrict__ Bm,
    const float* __restrict__ bias, float* __restrict__ C, int Nd, int mode,
    float* __restrict__ Qo, float* __restrict__ Ko, float* __restrict__ Vo)
{
    extern __shared__ char smem[];
    const uint32_t sb = smem_u32(smem);

    const int tid  = threadIdx.x;
    const int lane = tid & 31;
    const int wid  = tid >> 5;
    const int wm   = wid & 1;
    const int wn   = wid >> 1;
    const int g    = lane >> 2;
    const int tg   = lane & 3;

    const int bm = blockIdx.y * 128;
    const int bn = blockIdx.x * 128;

    const int a_row = wm * 64 + (lane & 15);
    const int a_kc  = (lane >> 4) * 8;
    const int b_row = wn * 32 + ((lane >> 4) << 3) + (lane & 7);
    const int b_kc  = ((lane >> 3) & 1) * 8;

    // loader: 3 tiles x 512 granules; j pairs map to fixed tiles
    auto load_chunk = [&](int k0, int stage) {
        const uint32_t dbase = sb + stage * STAGE_B;
#pragma unroll
        for (int j = 0; j < 6; j++) {
            const int tile = j >> 1;                 // 0:Ahi 1:Alo 2:B
            const int within = tid + (j & 1) * 256;  // 0..511
            const int row = within >> 2;
            const int gr  = within & 3;
            const __half* srcb = (tile == 0) ? Ahi : (tile == 1) ? Alo : Bm;
            const int rowb = (tile < 2) ? bm : bn;
            const void* src = srcb + (size_t)(rowb + row) * Ddim + k0 + gr * 8;
            cp_async16(dbase + (uint32_t)(tile * TILE_B + row * (LDK * 2) + gr * 16), src);
        }
        CP_COMMIT();
    };

    float acc[4][4][4];
#pragma unroll
    for (int i = 0; i < 4; i++)
#pragma unroll
        for (int j = 0; j < 4; j++)
#pragma unroll
            for (int q = 0; q < 4; q++) acc[i][j][q] = 0.f;

    load_chunk(0, 0);

    const int NCH = Ddim / BK;   // 24
    for (int c = 0; c < NCH; c++) {
        cp_wait<0>();
        __syncthreads();
        if (c + 1 < NCH) load_chunk((c + 1) * BK, (c + 1) & 1);

        const uint32_t st = sb + (c & 1) * STAGE_B;

#pragma unroll
        for (int ks = 0; ks < 2; ks++) {
            const int kcA = ks * 16 + a_kc;
            const int kcB = ks * 16 + b_kc;
            uint32_t ah[4][4], al[4][4];
#pragma unroll
            for (int mt = 0; mt < 4; mt++) {
                uint32_t addr = st + (uint32_t)(((a_row + mt * 16) * LDK + kcA) * 2);
                ldsm4(ah[mt][0], ah[mt][1], ah[mt][2], ah[mt][3], addr + OFF_AHI);
                ldsm4(al[mt][0], al[mt][1], al[mt][2], al[mt][3], addr + OFF_ALO);
            }
#pragma unroll
            for (int p = 0; p < 2; p++) {
                uint32_t baddr = st + (uint32_t)(((b_row + p * 16) * LDK + kcB) * 2);
                uint32_t bh[2][2];
                ldsm4(bh[0][0], bh[0][1], bh[1][0], bh[1][1], baddr + OFF_B);
#pragma unroll
                for (int q = 0; q < 2; q++) {
                    const int nt = p * 2 + q;
#pragma unroll
                    for (int mt = 0; mt < 4; mt++) {
                        mma16816h(acc[mt][nt], ah[mt][0], ah[mt][1], ah[mt][2], ah[mt][3],
                                  bh[q][0], bh[q][1]);
                        mma16816h(acc[mt][nt], al[mt][0], al[mt][1], al[mt][2], al[mt][3],
                                  bh[q][0], bh[q][1]);
                    }
                }
            }
        }
    }

    if (mode == 1) {
#pragma unroll
        for (int mt = 0; mt < 4; mt++) {
            int r0 = bm + wm * 64 + mt * 16 + g;
#pragma unroll
            for (int nt = 0; nt < 4; nt++) {
                int c0 = bn + wn * 32 + nt * 8 + tg * 2;
                float b0 = bias[c0], b1 = bias[c0 + 1];
                float2 v0 = make_float2(acc[mt][nt][0] + b0, acc[mt][nt][1] + b1);
                float2 v1 = make_float2(acc[mt][nt][2] + b0, acc[mt][nt][3] + b1);
                *(float2*)(C + (size_t)r0 * Nd + c0) = v0;
                *(float2*)(C + (size_t)(r0 + 8) * Nd + c0) = v1;
            }
        }
    } else {
#pragma unroll
        for (int nt = 0; nt < 4; nt++) {
            int c0 = bn + wn * 32 + nt * 8 + tg * 2;
            int t = c0 / Ddim;
            int rem = c0 - t * Ddim;
            int h = rem >> 6, d = rem & 63;
            float* dst = (t == 0) ? Qo : (t == 1) ? Ko : Vo;
#pragma unroll
            for (int mt = 0; mt < 4; mt++) {
                int r0 = bm + wm * 64 + mt * 16 + g;
#pragma unroll
                for (int rr = 0; rr < 2; rr++) {
                    int r = r0 + rr * 8;
                    int b = r / Ndim;
                    int n = r - b * Ndim;
                    size_t off = (((size_t)(b * Hh + h)) * Ndim + n) * HD + d;
                    float2 v = make_float2(acc[mt][nt][2 * rr], acc[mt][nt][2 * rr + 1]);
                    *(float2*)(dst + off) = v;
                }
            }
        }
    }
}

// ---------------------------------------------------------------------------
// fp32 -> fp16 hi/lo split, and fp32 -> fp16 single
// ---------------------------------------------------------------------------
__global__ void cvt_split_h(const float* __restrict__ in,
                            __half* __restrict__ hi,
                            __half* __restrict__ lo, size_t n)
{
    size_t i = (size_t)blockIdx.x * 256 + threadIdx.x;
    if (i >= n) return;
    float v = in[i];
    __half h = __float2half(v);
    hi[i] = h;
    lo[i] = __float2half(v - __half2float(h));
}

__global__ void cvt_h(const float* __restrict__ in, __half* __restrict__ out, size_t n)
{
    size_t i = (size_t)blockIdx.x * 256 + threadIdx.x;
    if (i >= n) return;
    out[i] = __float2half(in[i]);
}

// ---------------------------------------------------------------------------
// MMA flash spatial attention (bf16-split internally, unchanged from R10):
// 768 groups (heads 0..5), 196 q x 196 k, d=64. 13 warps. Output epilogue
// writes fp16 hi/lo wf (head-interleaved).
// ---------------------------------------------------------------------------
#define AT_T    416
#define MPAD    208
#define LDA     72
#define OQH     0
#define OQL     (MPAD * LDA * 2)
#define OKH     (2 * MPAD * LDA * 2)
#define OKL     (OKH + 64 * LDA * 2)
#define OVH     (OKL + 64 * LDA * 2)
#define OVL     (OVH + 64 * LDA * 2)
#define ATSMEM  (OVL + 64 * LDA * 2)      // 96768

__global__ __launch_bounds__(AT_T, 1) void attn_spatial_k()
{
    extern __shared__ char smem[];
    const uint32_t sb = smem_u32(smem);
    __nv_bfloat16* Qhi = (__nv_bfloat16*)(smem + OQH);
    __nv_bfloat16* Qlo = (__nv_bfloat16*)(smem + OQL);
    __nv_bfloat16* Khi = (__nv_bfloat16*)(smem + OKH);
    __nv_bfloat16* Klo = (__nv_bfloat16*)(smem + OKL);
    __nv_bfloat16* Vth = (__nv_bfloat16*)(smem + OVH);
    __nv_bfloat16* Vtl = (__nv_bfloat16*)(smem + OVL);

    const int grp = blockIdx.x;
    const int b = grp / 96;
    const int h = (grp % 96) / 16;
    const int f = grp % 16;
    const size_t base = (((size_t)(b * Hh + h)) * Ndim + f * Pdim) * HD;

    const int tid  = threadIdx.x;
    const int lane = tid & 31;
    const int wid  = tid >> 5;
    const int gq   = lane >> 2;
    const int tg   = lane & 3;

    for (int idx = tid; idx < MPAD * 64; idx += AT_T) {
        int r = idx >> 6, c = idx & 63;
        float v = (r < Pdim) ? g_q[base + (size_t)r * HD + c] : 0.f;
        __nv_bfloat16 hv = __float2bfloat16(v);
        Qhi[r * LDA + c] = hv;
        Qlo[r * LDA + c] = __float2bfloat16(v - __bfloat162float(hv));
    }
    __syncthreads();

    uint32_t qh[4][4], ql[4][4];
    {
        const int arow = wid * 16 + (lane & 15);
        const int acol = (lane >> 4) * 8;
#pragma unroll
        for (int kb = 0; kb < 4; kb++) {
            uint32_t addr = sb + (uint32_t)((arow * LDA + kb * 16 + acol) * 2);
            ldsm4(qh[kb][0], qh[kb][1], qh[kb][2], qh[kb][3], addr + OQH);
            ldsm4(ql[kb][0], ql[kb][1], ql[kb][2], ql[kb][3], addr + OQL);
        }
    }

    float ofr[8][4];
#pragma unroll
    for (int j = 0; j < 8; j++)
#pragma unroll
        for (int q = 0; q < 4; q++) ofr[j][q] = 0.f;
    float mx0 = -1e30f, mx1 = -1e30f, ls0 = 0.f, ls1 = 0.f;
    const float scale = 0.125f;

    const int brow = ((lane >> 4) << 3) + (lane & 7);
    const int bcol = ((lane >> 3) & 1) * 8;

    for (int ch = 0; ch < 4; ch++) {
        __syncthreads();
        const int kbase = ch * 64;
        for (int idx = tid; idx < 64 * 64; idx += AT_T) {
            int r = idx >> 6, c = idx & 63;
            int key = kbase + r;
            float kv = (key < Pdim) ? g_k[base + (size_t)key * HD + c] : 0.f;
            __nv_bfloat16 khv = __float2bfloat16(kv);
            Khi[r * LDA + c] = khv;
            Klo[r * LDA + c] = __float2bfloat16(kv - __bfloat162float(khv));
            float vv = (key < Pdim) ? g_v[base + (size_t)key * HD + c] : 0.f;
            __nv_bfloat16 vhv = __float2bfloat16(vv);
            Vth[c * LDA + r] = vhv;
            Vtl[c * LDA + r] = __float2bfloat16(vv - __bfloat162float(vhv));
        }
        __syncthreads();

        float sfr[8][4];
#pragma unroll
        for (int j = 0; j < 8; j++)
#pragma unroll
            for (int q = 0; q < 4; q++) sfr[j][q] = 0.f;

#pragma unroll
        for (int kb = 0; kb < 4; kb++) {
#pragma unroll
            for (int p = 0; p < 4; p++) {
                uint32_t ka = sb + (uint32_t)(((p * 16 + brow) * LDA + kb * 16 + bcol) * 2);
                uint32_t bh0, bh1, bh2, bh3, bl0, bl1, bl2, bl3;
                ldsm4(bh0, bh1, bh2, bh3, ka + OKH);
                ldsm4(bl0, bl1, bl2, bl3, ka + OKL);
                mma16816(sfr[2 * p], qh[kb][0], qh[kb][1], qh[kb][2], qh[kb][3], bh0, bh1);
                mma16816(sfr[2 * p], qh[kb][0], qh[kb][1], qh[kb][2], qh[kb][3], bl0, bl1);
                mma16816(sfr[2 * p], ql[kb][0], ql[kb][1], ql[kb][2], ql[kb][3], bh0, bh1);
                mma16816(sfr[2 * p + 1], qh[kb][0], qh[kb][1], qh[kb][2], qh[kb][3], bh2, bh3);
                mma16816(sfr[2 * p + 1], qh[kb][0], qh[kb][1], qh[kb][2], qh[kb][3], bl2, bl3);
                mma16816(sfr[2 * p + 1], ql[kb][0], ql[kb][1], ql[kb][2], ql[kb][3], bh2, bh3);
            }
        }

        const int nvalid = Pdim - kbase;
#pragma unroll
        for (int j = 0; j < 8; j++)
#pragma unroll
            for (int q = 0; q < 4; q++) {
                int key = j * 8 + 2 * tg + (q & 1);
                sfr[j][q] = (key < nvalid) ? sfr[j][q] * scale : -1e30f;
            }

        float rm0 = -1e30f, rm1 = -1e30f;
#pragma unroll
        for (int j = 0; j < 8; j++) {
            rm0 = fmaxf(rm0, fmaxf(sfr[j][0], sfr[j][1]));
            rm1 = fmaxf(rm1, fmaxf(sfr[j][2], sfr[j][3]));
        }
        rm0 = fmaxf(rm0, __shfl_xor_sync(0xFFFFFFFFu, rm0, 1));
        rm0 = fmaxf(rm0, __shfl_xor_sync(0xFFFFFFFFu, rm0, 2));
        rm1 = fmaxf(rm1, __shfl_xor_sync(0xFFFFFFFFu, rm1, 1));
        rm1 = fmaxf(rm1, __shfl_xor_sync(0xFFFFFFFFu, rm1, 2));
        float nm0 = fmaxf(mx0, rm0), nm1 = fmaxf(mx1, rm1);
        float c0 = __expf(mx0 - nm0), c1 = __expf(mx1 - nm1);
        mx0 = nm0; mx1 = nm1;
        ls0 *= c0; ls1 *= c1;
#pragma unroll
        for (int j = 0; j < 8; j++) {
            ofr[j][0] *= c0; ofr[j][1] *= c0;
            ofr[j][2] *= c1; ofr[j][3] *= c1;
        }

        float rs0 = 0.f, rs1 = 0.f;
#pragma unroll
        for (int j = 0; j < 8; j++) {
            float p0 = __expf(sfr[j][0] - nm0);
            float p1 = __expf(sfr[j][1] - nm0);
            float p2 = __expf(sfr[j][2] - nm1);
            float p3 = __expf(sfr[j][3] - nm1);
            rs0 += p0 + p1; rs1 += p2 + p3;
            sfr[j][0] = p0; sfr[j][1] = p1; sfr[j][2] = p2; sfr[j][3] = p3;
        }
        rs0 += __shfl_xor_sync(0xFFFFFFFFu, rs0, 1);
        rs0 += __shfl_xor_sync(0xFFFFFFFFu, rs0, 2);
        rs1 += __shfl_xor_sync(0xFFFFFFFFu, rs1, 1);
        rs1 += __shfl_xor_sync(0xFFFFFFFFu, rs1, 2);
        ls0 += rs0; ls1 += rs1;

#pragma unroll
        for (int kb = 0; kb < 4; kb++) {
            uint32_t pah[4], pal[4];
#pragma unroll
            for (int half = 0; half < 2; half++) {
                const int j = 2 * kb + half;
                float p0 = sfr[j][0], p1 = sfr[j][1], p2 = sfr[j][2], p3 = sfr[j][3];
                __nv_bfloat16 h0 = __float2bfloat16(p0);
                __nv_bfloat16 h1 = __float2bfloat16(p1);
                __nv_bfloat16 h2 = __float2bfloat16(p2);
                __nv_bfloat16 h3 = __float2bfloat16(p3);
                pah[2 * half + 0] = pack_bf16x2(__bfloat162float(h0), __bfloat162float(h1));
                pah[2 * half + 1] = pack_bf16x2(__bfloat162float(h2), __bfloat162float(h3));
                pal[2 * half + 0] = pack_bf16x2(p0 - __bfloat162float(h0), p1 - __bfloat162float(h1));
                pal[2 * half + 1] = pack_bf16x2(p2 - __bfloat162float(h2), p3 - __bfloat162float(h3));
            }
#pragma unroll
            for (int p = 0; p < 4; p++) {
                uint32_t va = sb + (uint32_t)(((p * 16 + brow) * LDA + kb * 16 + bcol) * 2);
                uint32_t vh0, vh1, vh2, vh3, vl0, vl1, vl2, vl3;
                ldsm4(vh0, vh1, vh2, vh3, va + OVH);
                ldsm4(vl0, vl1, vl2, vl3, va + OVL);
                mma16816(ofr[2 * p], pah[0], pah[1], pah[2], pah[3], vh0, vh1);
                mma16816(ofr[2 * p], pah[0], pah[1], pah[2], pah[3], vl0, vl1);
                mma16816(ofr[2 * p], pal[0], pal[1], pal[2], pal[3], vh0, vh1);
                mma16816(ofr[2 * p + 1], pah[0], pah[1], pah[2], pah[3], vh2, vh3);
                mma16816(ofr[2 * p + 1], pah[0], pah[1], pah[2], pah[3], vl2, vl3);
                mma16816(ofr[2 * p + 1], pal[0], pal[1], pal[2], pal[3], vh2, vh3);
            }
        }
    }

    // epilogue: normalize, fp16-split, store head-interleaved
    float inv0 = 1.f / ls0, inv1 = 1.f / ls1;
    const int r0 = wid * 16 + gq;
    const int r1 = r0 + 8;
    if (r0 < Pdim) {
        const size_t ob = ((size_t)b * Ndim + (f * Pdim + r0)) * Ddim + h * HD;
#pragma unroll
        for (int j = 0; j < 8; j++) {
            float v0 = ofr[j][0] * inv0, v1 = ofr[j][1] * inv0;
            __half h0 = __float2half(v0);
            __half h1 = __float2half(v1);
            __half2 hv; hv.x = h0; hv.y = h1;
            __half2 lv;
            lv.x = __float2half(v0 - __half2float(h0));
            lv.y = __float2half(v1 - __half2float(h1));
            *(__half2*)(g_wf_hi + ob + j * 8 + 2 * tg) = hv;
            *(__half2*)(g_wf_lo + ob + j * 8 + 2 * tg) = lv;
        }
    }
    if (r1 < Pdim) {
        const size_t ob = ((size_t)b * Ndim + (f * Pdim + r1)) * Ddim + h * HD;
#pragma unroll
        for (int j = 0; j < 8; j++) {
            float v0 = ofr[j][2] * inv1, v1 = ofr[j][3] * inv1;
            __half h0 = __float2half(v0);
            __half h1 = __float2half(v1);
            __half2 hv; hv.x = h0; hv.y = h1;
            __half2 lv;
            lv.x = __float2half(v0 - __half2float(h0));
            lv.y = __float2half(v1 - __half2float(h1));
            *(__half2*)(g_wf_hi + ob + j * 8 + 2 * tg) = hv;
            *(__half2*)(g_wf_lo + ob + j * 8 + 2 * tg) = lv;
        }
    }
}

// ---------------------------------------------------------------------------
// Temporal attention: heads 6..11, groups of 16 rows. Writes fp16 wf.
// ---------------------------------------------------------------------------
__global__ __launch_bounds__(128) void attn_temporal_k()
{
    int tid = blockIdx.x * 128 + threadIdx.x;
    const int TOT = Bdim * 6 * Ndim;
    if (tid >= TOT) return;
    int b = tid / (6 * Ndim);
    int rr = tid - b * (6 * Ndim);
    int h = 6 + rr / Ndim;
    int n = rr % Ndim;
    int n0 = n & ~15;
    size_t row = (((size_t)(b * Hh + h)) * Ndim + n) * HD;
    size_t gb  = (((size_t)(b * Hh + h)) * Ndim + n0) * HD;

    float4 q4[16];
    const float4* qp = (const float4*)(g_q + row);
#pragma unroll
    for (int i = 0; i < 16; i++) q4[i] = qp[i];

    float s[16];
    float mx = -1e30f;
#pragma unroll
    for (int f = 0; f < 16; f++) {
        const float4* kp = (const float4*)(g_k + gb + (size_t)f * HD);
        float a = 0.f;
#pragma unroll
        for (int i = 0; i < 16; i++) {
            float4 kv = kp[i];
            a = fmaf(q4[i].x, kv.x, a);
            a = fmaf(q4[i].y, kv.y, a);
            a = fmaf(q4[i].z, kv.z, a);
            a = fmaf(q4[i].w, kv.w, a);
        }
        s[f] = a * 0.125f;
        mx = fmaxf(mx, s[f]);
    }
    float lsum = 0.f;
#pragma unroll
    for (int f = 0; f < 16; f++) { s[f] = __expf(s[f] - mx); lsum += s[f]; }
    float inv = 1.f / lsum;
#pragma unroll
    for (int f = 0; f < 16; f++) s[f] *= inv;

    const size_t obase = ((size_t)b * Ndim + n) * Ddim + h * HD;
#pragma unroll
    for (int ch = 0; ch < 4; ch++) {
        float4 a4[4];
#pragma unroll
        for (int i = 0; i < 4; i++) a4[i] = make_float4(0.f, 0.f, 0.f, 0.f);
#pragma unroll
        for (int f = 0; f < 16; f++) {
            float p = s[f];
            const float4* vp = (const float4*)(g_v + gb + (size_t)f * HD + ch * 16);
#pragma unroll
            for (int i = 0; i < 4; i++) {
                float4 vv = vp[i];
                a4[i].x = fmaf(p, vv.x, a4[i].x);
                a4[i].y = fmaf(p, vv.y, a4[i].y);
                a4[i].z = fmaf(p, vv.z, a4[i].z);
                a4[i].w = fmaf(p, vv.w, a4[i].w);
            }
        }
#pragma unroll
        for (int i = 0; i < 4; i++) {
            float vals[4] = { a4[i].x, a4[i].y, a4[i].z, a4[i].w };
#pragma unroll
            for (int j = 0; j < 4; j += 2) {
                float v0 = vals[j], v1 = vals[j + 1];
                __half h0 = __float2half(v0);
                __half h1 = __float2half(v1);
                __half2 hv; hv.x = h0; hv.y = h1;
                __half2 lv;
                lv.x = __float2half(v0 - __half2float(h0));
                lv.y = __float2half(v1 - __half2float(h1));
                size_t o = obase + ch * 16 + i * 4 + j;
                *(__half2*)(g_wf_hi + o) = hv;
                *(__half2*)(g_wf_lo + o) = lv;
            }
        }
    }
}

// ---------------------------------------------------------------------------
// Launch
// ---------------------------------------------------------------------------
extern "C" void kernel_launch(void* const* d_in, const int* in_sizes, int n_in,
                              void* d_out, int out_size)
{
    const float* x      = (const float*)d_in[0];
    const float* w_qkv  = (const float*)d_in[1];
    const float* w_proj = (const float*)d_in[2];
    const float* b_proj = (const float*)d_in[3];
    float* out = (float*)d_out;

    float *p_q, *p_k, *p_v;
    __half *p_xhi, *p_xlo, *p_wqkv, *p_wproj, *p_wfhi, *p_wflo;
    cudaGetSymbolAddress((void**)&p_q, g_q);
    cudaGetSymbolAddress((void**)&p_k, g_k);
    cudaGetSymbolAddress((void**)&p_v, g_v);
    cudaGetSymbolAddress((void**)&p_xhi, g_xhi);
    cudaGetSymbolAddress((void**)&p_xlo, g_xlo);
    cudaGetSymbolAddress((void**)&p_wqkv, g_wqkv);
    cudaGetSymbolAddress((void**)&p_wproj, g_wproj);
    cudaGetSymbolAddress((void**)&p_wfhi, g_wf_hi);
    cudaGetSymbolAddress((void**)&p_wflo, g_wf_lo);

    cudaFuncSetAttribute(tgemm_k, cudaFuncAttributeMaxDynamicSharedMemorySize, GSMEM);
    cudaFuncSetAttribute(attn_spatial_k, cudaFuncAttributeMaxDynamicSharedMemorySize, ATSMEM);

    // 0) fp16 conversions: x split hi/lo; weights single
    cvt_split_h<<<(unsigned)((MD_ELEMS + 255) / 256), 256>>>(x, p_xhi, p_xlo, MD_ELEMS);
    cvt_h<<<(unsigned)(((size_t)E3 * Ddim + 255) / 256), 256>>>(
        w_qkv, p_wqkv, (size_t)E3 * Ddim);
    cvt_h<<<(unsigned)(((size_t)Ddim * Ddim + 255) / 256), 256>>>(
        w_proj, p_wproj, (size_t)Ddim * Ddim);

    // 1) qkv GEMM (2-pass fp16) with fused scatter into q/k/v head layout
    tgemm_k<<<dim3(E3 / 128, Mrows / 128), 256, GSMEM>>>(
        p_xhi, p_xlo, p_wqkv, nullptr, nullptr, E3, 0, p_q, p_k, p_v);

    // 2) MMA flash spatial attention
    attn_spatial_k<<<768, AT_T, ATSMEM>>>();

    // 3) temporal attention
    attn_temporal_k<<<(Bdim * 6 * Ndim) / 128, 128>>>();

    // 4) out = wf @ w_proj^T + b_proj (2-pass fp16)
    tgemm_k<<<dim3(Ddim / 128, Mrows / 128), 256, GSMEM>>>(
        p_wfhi, p_wflo, p_wproj, b_proj, out, Ddim, 1,
        nullptr, nullptr, nullptr);
}

// round 13
// speedup vs baseline: 2.0282x; 1.1734x over previous
#include <cuda_runtime.h>
#include <cuda_fp16.h>
#include <cstdint>
#include <cstddef>

// ---------------------------------------------------------------------------
// Problem constants
// ---------------------------------------------------------------------------
#define Bdim  8
#define Fdim  16
#define Pdim  196
#define Ddim  768
#define Hh    12
#define HD    64
#define Ndim  3136              // F*P
#define Mrows 25088             // B*N
#define E3    2304              // 3*D

#define HEAD_ELEMS ((size_t)Bdim * Hh * Ndim * HD)
#define MD_ELEMS   ((size_t)Mrows * Ddim)

// Scratch (__device__ globals; allocation-free rule)
__device__ float g_q[HEAD_ELEMS];
__device__ float g_k[HEAD_ELEMS];
__device__ float g_v[HEAD_ELEMS];

__device__ __half g_xhi[MD_ELEMS];
__device__ __half g_xlo[MD_ELEMS];
__device__ __half g_wqkv[(size_t)E3 * Ddim];
__device__ __half g_wproj[(size_t)Ddim * Ddim];
__device__ __half g_wf[MD_ELEMS];

// ---------------------------------------------------------------------------
// helpers
// ---------------------------------------------------------------------------
__device__ __forceinline__ void cp_async16(uint32_t dst, const void* src) {
    asm volatile("cp.async.cg.shared.global [%0], [%1], 16;"
                 :: "r"(dst), "l"(src) : "memory");
}
#define CP_COMMIT() asm volatile("cp.async.commit_group;" ::: "memory")
template <int N> __device__ __forceinline__ void cp_wait() {
    asm volatile("cp.async.wait_group %0;" :: "n"(N) : "memory");
}
__device__ __forceinline__ uint32_t smem_u32(const void* p) {
    uint32_t a;
    asm("{ .reg .u64 t; cvta.to.shared.u64 t, %1; cvt.u32.u64 %0, t; }"
        : "=r"(a) : "l"(p));
    return a;
}

// fp16 mma
__device__ __forceinline__ void mma16816h(float* d,
                                          uint32_t a0, uint32_t a1, uint32_t a2, uint32_t a3,
                                          uint32_t b0, uint32_t b1) {
    asm volatile(
        "mma.sync.aligned.m16n8k16.row.col.f32.f16.f16.f32 "
        "{%0,%1,%2,%3}, {%4,%5,%6,%7}, {%8,%9}, {%0,%1,%2,%3};"
        : "+f"(d[0]), "+f"(d[1]), "+f"(d[2]), "+f"(d[3])
        : "r"(a0), "r"(a1), "r"(a2), "r"(a3), "r"(b0), "r"(b1));
}

__device__ __forceinline__ void ldsm4(uint32_t& r0, uint32_t& r1,
                                      uint32_t& r2, uint32_t& r3, uint32_t addr) {
    asm volatile("ldmatrix.sync.aligned.m8n8.x4.shared.b16 {%0,%1,%2,%3}, [%4];"
                 : "=r"(r0), "=r"(r1), "=r"(r2), "=r"(r3) : "r"(addr));
}

__device__ __forceinline__ uint32_t pack_h2(float x, float y) {
    __half2 t = __floats2half2_rn(x, y);
    return *(uint32_t*)&t;
}

// ---------------------------------------------------------------------------
// HMMA GEMM (fp16):  C = (Ahi[+Alo])[M,768] * B[N,768]^T
// SPLIT=true: A hi/lo 2-pass (GEMM1). SPLIT=false: single-pass (GEMM2).
// 128x128x32 CTA tile, 256 threads, warp grid 2(M)x4(N), warp tile 64x32.
// LDK=40 (80B rows, conflict-free ldmatrix), 2-stage cp.async, single sync.
// mode 0: scatter epilogue into q/k/v head layout; mode 1: C + bias.
// ---------------------------------------------------------------------------
#define BK       32
#define LDK      40
#define TILE_B   (128 * LDK * 2)          // 10240

template <bool SPLIT>
__global__ __launch_bounds__(256, 2) void tgemm_k(
    const __half* __restrict__ Ahi, const __half* __restrict__ Alo,
    const __half* __restrict__ Bm,
    const float* __restrict__ bias, float* __restrict__ C, int Nd, int mode,
    float* __restrict__ Qo, float* __restrict__ Ko, float* __restrict__ Vo)
{
    constexpr int NT      = SPLIT ? 3 : 2;
    constexpr int STAGE_B = NT * TILE_B;
    constexpr int OFF_ALO = TILE_B;
    constexpr int OFF_B   = (SPLIT ? 2 : 1) * TILE_B;

    extern __shared__ char smem[];
    const uint32_t sb = smem_u32(smem);

    const int tid  = threadIdx.x;
    const int lane = tid & 31;
    const int wid  = tid >> 5;
    const int wm   = wid & 1;
    const int wn   = wid >> 1;
    const int g    = lane >> 2;
    const int tg   = lane & 3;

    const int bm = blockIdx.y * 128;
    const int bn = blockIdx.x * 128;

    const int a_row = wm * 64 + (lane & 15);
    const int a_kc  = (lane >> 4) * 8;
    const int b_row = wn * 32 + ((lane >> 4) << 3) + (lane & 7);
    const int b_kc  = ((lane >> 3) & 1) * 8;

    auto load_chunk = [&](int k0, int stage) {
        const uint32_t dbase = sb + stage * STAGE_B;
#pragma unroll
        for (int j = 0; j < 2 * NT; j++) {
            const int tile = j >> 1;                 // 0:Ahi [1:Alo] last:B
            const int within = tid + (j & 1) * 256;  // 0..511
            const int row = within >> 2;
            const int gr  = within & 3;
            const __half* srcb = (tile == 0) ? Ahi
                               : (SPLIT && tile == 1) ? Alo : Bm;
            const int rowb = (tile < NT - 1) ? bm : bn;
            const void* src = srcb + (size_t)(rowb + row) * Ddim + k0 + gr * 8;
            cp_async16(dbase + (uint32_t)(tile * TILE_B + row * (LDK * 2) + gr * 16), src);
        }
        CP_COMMIT();
    };

    float acc[4][4][4];
#pragma unroll
    for (int i = 0; i < 4; i++)
#pragma unroll
        for (int j = 0; j < 4; j++)
#pragma unroll
            for (int q = 0; q < 4; q++) acc[i][j][q] = 0.f;

    load_chunk(0, 0);

    const int NCH = Ddim / BK;   // 24
    for (int c = 0; c < NCH; c++) {
        cp_wait<0>();
        __syncthreads();
        if (c + 1 < NCH) load_chunk((c + 1) * BK, (c + 1) & 1);

        const uint32_t st = sb + (c & 1) * STAGE_B;

#pragma unroll
        for (int ks = 0; ks < 2; ks++) {
            const int kcA = ks * 16 + a_kc;
            const int kcB = ks * 16 + b_kc;
            uint32_t ah[4][4], al[4][4];
#pragma unroll
            for (int mt = 0; mt < 4; mt++) {
                uint32_t addr = st + (uint32_t)(((a_row + mt * 16) * LDK + kcA) * 2);
                ldsm4(ah[mt][0], ah[mt][1], ah[mt][2], ah[mt][3], addr);
                if (SPLIT)
                    ldsm4(al[mt][0], al[mt][1], al[mt][2], al[mt][3], addr + OFF_ALO);
            }
#pragma unroll
            for (int p = 0; p < 2; p++) {
                uint32_t baddr = st + (uint32_t)(((b_row + p * 16) * LDK + kcB) * 2);
                uint32_t bh[2][2];
                ldsm4(bh[0][0], bh[0][1], bh[1][0], bh[1][1], baddr + OFF_B);
#pragma unroll
                for (int q = 0; q < 2; q++) {
                    const int nt = p * 2 + q;
#pragma unroll
                    for (int mt = 0; mt < 4; mt++) {
                        mma16816h(acc[mt][nt], ah[mt][0], ah[mt][1], ah[mt][2], ah[mt][3],
                                  bh[q][0], bh[q][1]);
                        if (SPLIT)
                            mma16816h(acc[mt][nt], al[mt][0], al[mt][1], al[mt][2], al[mt][3],
                                      bh[q][0], bh[q][1]);
                    }
                }
            }
        }
    }

    if (mode == 1) {
#pragma unroll
        for (int mt = 0; mt < 4; mt++) {
            int r0 = bm + wm * 64 + mt * 16 + g;
#pragma unroll
            for (int nt = 0; nt < 4; nt++) {
                int c0 = bn + wn * 32 + nt * 8 + tg * 2;
                float b0 = bias[c0], b1 = bias[c0 + 1];
                float2 v0 = make_float2(acc[mt][nt][0] + b0, acc[mt][nt][1] + b1);
                float2 v1 = make_float2(acc[mt][nt][2] + b0, acc[mt][nt][3] + b1);
                *(float2*)(C + (size_t)r0 * Nd + c0) = v0;
                *(float2*)(C + (size_t)(r0 + 8) * Nd + c0) = v1;
            }
        }
    } else {
#pragma unroll
        for (int nt = 0; nt < 4; nt++) {
            int c0 = bn + wn * 32 + nt * 8 + tg * 2;
            int t = c0 / Ddim;
            int rem = c0 - t * Ddim;
            int h = rem >> 6, d = rem & 63;
            float* dst = (t == 0) ? Qo : (t == 1) ? Ko : Vo;
#pragma unroll
            for (int mt = 0; mt < 4; mt++) {
                int r0 = bm + wm * 64 + mt * 16 + g;
#pragma unroll
                for (int rr = 0; rr < 2; rr++) {
                    int r = r0 + rr * 8;
                    int b = r / Ndim;
                    int n = r - b * Ndim;
                    size_t off = (((size_t)(b * Hh + h)) * Ndim + n) * HD + d;
                    float2 v = make_float2(acc[mt][nt][2 * rr], acc[mt][nt][2 * rr + 1]);
                    *(float2*)(dst + off) = v;
                }
            }
        }
    }
}

// ---------------------------------------------------------------------------
// fp32 -> fp16 hi/lo split, and fp32 -> fp16 single
// ---------------------------------------------------------------------------
__global__ void cvt_split_h(const float* __restrict__ in,
                            __half* __restrict__ hi,
                            __half* __restrict__ lo, size_t n)
{
    size_t i = (size_t)blockIdx.x * 256 + threadIdx.x;
    if (i >= n) return;
    float v = in[i];
    __half h = __float2half(v);
    hi[i] = h;
    lo[i] = __float2half(v - __half2float(h));
}

__global__ void cvt_h(const float* __restrict__ in, __half* __restrict__ out, size_t n)
{
    size_t i = (size_t)blockIdx.x * 256 + threadIdx.x;
    if (i >= n) return;
    out[i] = __float2half(in[i]);
}

// ---------------------------------------------------------------------------
// MMA flash spatial attention (fp16): 768 groups (heads 0..5), 196x196, d=64.
// Q split hi/lo (2-pass S vs single K); P split hi/lo (2-pass PV vs single
// V^T). 13 warps; warp = one 16-row m-tile. Output -> g_wf (single fp16).
// ---------------------------------------------------------------------------
#define AT_T    416
#define MPAD    208
#define LDA     72
#define OQH     0
#define OQL     (MPAD * LDA * 2)          // 29952
#define OKH     (2 * MPAD * LDA * 2)      // 59904
#define OVH     (OKH + 64 * LDA * 2)      // 69120
#define ATSMEM  (OVH + 64 * LDA * 2)      // 78336

__global__ __launch_bounds__(AT_T, 1) void attn_spatial_k()
{
    extern __shared__ char smem[];
    const uint32_t sb = smem_u32(smem);
    __half* Qhi = (__half*)(smem + OQH);
    __half* Qlo = (__half*)(smem + OQL);
    __half* Ks  = (__half*)(smem + OKH);
    __half* Vt  = (__half*)(smem + OVH);

    const int grp = blockIdx.x;
    const int b = grp / 96;
    const int h = (grp % 96) / 16;
    const int f = grp % 16;
    const size_t base = (((size_t)(b * Hh + h)) * Ndim + f * Pdim) * HD;

    const int tid  = threadIdx.x;
    const int lane = tid & 31;
    const int wid  = tid >> 5;
    const int gq   = lane >> 2;
    const int tg   = lane & 3;

    for (int idx = tid; idx < MPAD * 64; idx += AT_T) {
        int r = idx >> 6, c = idx & 63;
        float v = (r < Pdim) ? g_q[base + (size_t)r * HD + c] : 0.f;
        __half hv = __float2half(v);
        Qhi[r * LDA + c] = hv;
        Qlo[r * LDA + c] = __float2half(v - __half2float(hv));
    }
    __syncthreads();

    uint32_t qh[4][4], ql[4][4];
    {
        const int arow = wid * 16 + (lane & 15);
        const int acol = (lane >> 4) * 8;
#pragma unroll
        for (int kb = 0; kb < 4; kb++) {
            uint32_t addr = sb + (uint32_t)((arow * LDA + kb * 16 + acol) * 2);
            ldsm4(qh[kb][0], qh[kb][1], qh[kb][2], qh[kb][3], addr + OQH);
            ldsm4(ql[kb][0], ql[kb][1], ql[kb][2], ql[kb][3], addr + OQL);
        }
    }

    float ofr[8][4];
#pragma unroll
    for (int j = 0; j < 8; j++)
#pragma unroll
        for (int q = 0; q < 4; q++) ofr[j][q] = 0.f;
    float mx0 = -1e30f, mx1 = -1e30f, ls0 = 0.f, ls1 = 0.f;
    const float scale = 0.125f;

    const int brow = ((lane >> 4) << 3) + (lane & 7);
    const int bcol = ((lane >> 3) & 1) * 8;

    for (int ch = 0; ch < 4; ch++) {
        __syncthreads();
        const int kbase = ch * 64;
        for (int idx = tid; idx < 64 * 64; idx += AT_T) {
            int r = idx >> 6, c = idx & 63;
            int key = kbase + r;
            float kv = (key < Pdim) ? g_k[base + (size_t)key * HD + c] : 0.f;
            Ks[r * LDA + c] = __float2half(kv);
            float vv = (key < Pdim) ? g_v[base + (size_t)key * HD + c] : 0.f;
            Vt[c * LDA + r] = __float2half(vv);
        }
        __syncthreads();

        float sfr[8][4];
#pragma unroll
        for (int j = 0; j < 8; j++)
#pragma unroll
            for (int q = 0; q < 4; q++) sfr[j][q] = 0.f;

#pragma unroll
        for (int kb = 0; kb < 4; kb++) {
#pragma unroll
            for (int p = 0; p < 4; p++) {
                uint32_t ka = sb + (uint32_t)(((p * 16 + brow) * LDA + kb * 16 + bcol) * 2);
                uint32_t bh0, bh1, bh2, bh3;
                ldsm4(bh0, bh1, bh2, bh3, ka + OKH);
                mma16816h(sfr[2 * p], qh[kb][0], qh[kb][1], qh[kb][2], qh[kb][3], bh0, bh1);
                mma16816h(sfr[2 * p], ql[kb][0], ql[kb][1], ql[kb][2], ql[kb][3], bh0, bh1);
                mma16816h(sfr[2 * p + 1], qh[kb][0], qh[kb][1], qh[kb][2], qh[kb][3], bh2, bh3);
                mma16816h(sfr[2 * p + 1], ql[kb][0], ql[kb][1], ql[kb][2], ql[kb][3], bh2, bh3);
            }
        }

        const int nvalid = Pdim - kbase;
#pragma unroll
        for (int j = 0; j < 8; j++)
#pragma unroll
            for (int q = 0; q < 4; q++) {
                int key = j * 8 + 2 * tg + (q & 1);
                sfr[j][q] = (key < nvalid) ? sfr[j][q] * scale : -1e30f;
            }

        float rm0 = -1e30f, rm1 = -1e30f;
#pragma unroll
        for (int j = 0; j < 8; j++) {
            rm0 = fmaxf(rm0, fmaxf(sfr[j][0], sfr[j][1]));
            rm1 = fmaxf(rm1, fmaxf(sfr[j][2], sfr[j][3]));
        }
        rm0 = fmaxf(rm0, __shfl_xor_sync(0xFFFFFFFFu, rm0, 1));
        rm0 = fmaxf(rm0, __shfl_xor_sync(0xFFFFFFFFu, rm0, 2));
        rm1 = fmaxf(rm1, __shfl_xor_sync(0xFFFFFFFFu, rm1, 1));
        rm1 = fmaxf(rm1, __shfl_xor_sync(0xFFFFFFFFu, rm1, 2));
        float nm0 = fmaxf(mx0, rm0), nm1 = fmaxf(mx1, rm1);
        float c0 = __expf(mx0 - nm0), c1 = __expf(mx1 - nm1);
        mx0 = nm0; mx1 = nm1;
        ls0 *= c0; ls1 *= c1;
#pragma unroll
        for (int j = 0; j < 8; j++) {
            ofr[j][0] *= c0; ofr[j][1] *= c0;
            ofr[j][2] *= c1; ofr[j][3] *= c1;
        }

        float rs0 = 0.f, rs1 = 0.f;
#pragma unroll
        for (int j = 0; j < 8; j++) {
            float p0 = __expf(sfr[j][0] - nm0);
            float p1 = __expf(sfr[j][1] - nm0);
            float p2 = __expf(sfr[j][2] - nm1);
            float p3 = __expf(sfr[j][3] - nm1);
            rs0 += p0 + p1; rs1 += p2 + p3;
            sfr[j][0] = p0; sfr[j][1] = p1; sfr[j][2] = p2; sfr[j][3] = p3;
        }
        rs0 += __shfl_xor_sync(0xFFFFFFFFu, rs0, 1);
        rs0 += __shfl_xor_sync(0xFFFFFFFFu, rs0, 2);
        rs1 += __shfl_xor_sync(0xFFFFFFFFu, rs1, 1);
        rs1 += __shfl_xor_sync(0xFFFFFFFFu, rs1, 2);
        ls0 += rs0; ls1 += rs1;

#pragma unroll
        for (int kb = 0; kb < 4; kb++) {
            uint32_t pah[4], pal[4];
#pragma unroll
            for (int half = 0; half < 2; half++) {
                const int j = 2 * kb + half;
                float p0 = sfr[j][0], p1 = sfr[j][1], p2 = sfr[j][2], p3 = sfr[j][3];
                __half h0 = __float2half(p0);
                __half h1 = __float2half(p1);
                __half h2 = __float2half(p2);
                __half h3 = __float2half(p3);
                pah[2 * half + 0] = pack_h2(__half2float(h0), __half2float(h1));
                pah[2 * half + 1] = pack_h2(__half2float(h2), __half2float(h3));
                pal[2 * half + 0] = pack_h2(p0 - __half2float(h0), p1 - __half2float(h1));
                pal[2 * half + 1] = pack_h2(p2 - __half2float(h2), p3 - __half2float(h3));
            }
#pragma unroll
            for (int p = 0; p < 4; p++) {
                uint32_t va = sb + (uint32_t)(((p * 16 + brow) * LDA + kb * 16 + bcol) * 2);
                uint32_t vh0, vh1, vh2, vh3;
                ldsm4(vh0, vh1, vh2, vh3, va + OVH);
                mma16816h(ofr[2 * p], pah[0], pah[1], pah[2], pah[3], vh0, vh1);
                mma16816h(ofr[2 * p], pal[0], pal[1], pal[2], pal[3], vh0, vh1);
                mma16816h(ofr[2 * p + 1], pah[0], pah[1], pah[2], pah[3], vh2, vh3);
                mma16816h(ofr[2 * p + 1], pal[0], pal[1], pal[2], pal[3], vh2, vh3);
            }
        }
    }

    float inv0 = 1.f / ls0, inv1 = 1.f / ls1;
    const int r0 = wid * 16 + gq;
    const int r1 = r0 + 8;
    if (r0 < Pdim) {
        const size_t ob = ((size_t)b * Ndim + (f * Pdim + r0)) * Ddim + h * HD;
#pragma unroll
        for (int j = 0; j < 8; j++) {
            __half2 hv = __floats2half2_rn(ofr[j][0] * inv0, ofr[j][1] * inv0);
            *(__half2*)(g_wf + ob + j * 8 + 2 * tg) = hv;
        }
    }
    if (r1 < Pdim) {
        const size_t ob = ((size_t)b * Ndim + (f * Pdim + r1)) * Ddim + h * HD;
#pragma unroll
        for (int j = 0; j < 8; j++) {
            __half2 hv = __floats2half2_rn(ofr[j][2] * inv1, ofr[j][3] * inv1);
            *(__half2*)(g_wf + ob + j * 8 + 2 * tg) = hv;
        }
    }
}

// ---------------------------------------------------------------------------
// Temporal attention: heads 6..11, groups of 16 rows. Writes g_wf (fp16).
// ---------------------------------------------------------------------------
__global__ __launch_bounds__(128) void attn_temporal_k()
{
    int tid = blockIdx.x * 128 + threadIdx.x;
    const int TOT = Bdim * 6 * Ndim;
    if (tid >= TOT) return;
    int b = tid / (6 * Ndim);
    int rr = tid - b * (6 * Ndim);
    int h = 6 + rr / Ndim;
    int n = rr % Ndim;
    int n0 = n & ~15;
    size_t row = (((size_t)(b * Hh + h)) * Ndim + n) * HD;
    size_t gb  = (((size_t)(b * Hh + h)) * Ndim + n0) * HD;

    float4 q4[16];
    const float4* qp = (const float4*)(g_q + row);
#pragma unroll
    for (int i = 0; i < 16; i++) q4[i] = qp[i];

    float s[16];
    float mx = -1e30f;
#pragma unroll
    for (int f = 0; f < 16; f++) {
        const float4* kp = (const float4*)(g_k + gb + (size_t)f * HD);
        float a = 0.f;
#pragma unroll
        for (int i = 0; i < 16; i++) {
            float4 kv = kp[i];
            a = fmaf(q4[i].x, kv.x, a);
            a = fmaf(q4[i].y, kv.y, a);
            a = fmaf(q4[i].z, kv.z, a);
            a = fmaf(q4[i].w, kv.w, a);
        }
        s[f] = a * 0.125f;
        mx = fmaxf(mx, s[f]);
    }
    float lsum = 0.f;
#pragma unroll
    for (int f = 0; f < 16; f++) { s[f] = __expf(s[f] - mx); lsum += s[f]; }
    float inv = 1.f / lsum;
#pragma unroll
    for (int f = 0; f < 16; f++) s[f] *= inv;

    const size_t obase = ((size_t)b * Ndim + n) * Ddim + h * HD;
#pragma unroll
    for (int ch = 0; ch < 4; ch++) {
        float4 a4[4];
#pragma unroll
        for (int i = 0; i < 4; i++) a4[i] = make_float4(0.f, 0.f, 0.f, 0.f);
#pragma unroll
        for (int f = 0; f < 16; f++) {
            float p = s[f];
            const float4* vp = (const float4*)(g_v + gb + (size_t)f * HD + ch * 16);
#pragma unroll
            for (int i = 0; i < 4; i++) {
                float4 vv = vp[i];
                a4[i].x = fmaf(p, vv.x, a4[i].x);
                a4[i].y = fmaf(p, vv.y, a4[i].y);
                a4[i].z = fmaf(p, vv.z, a4[i].z);
                a4[i].w = fmaf(p, vv.w, a4[i].w);
            }
        }
#pragma unroll
        for (int i = 0; i < 4; i++) {
            __half2 h0 = __floats2half2_rn(a4[i].x, a4[i].y);
            __half2 h1 = __floats2half2_rn(a4[i].z, a4[i].w);
            size_t o = obase + ch * 16 + i * 4;
            *(__half2*)(g_wf + o) = h0;
            *(__half2*)(g_wf + o + 2) = h1;
        }
    }
}

// ---------------------------------------------------------------------------
// Launch
// ---------------------------------------------------------------------------
extern "C" void kernel_launch(void* const* d_in, const int* in_sizes, int n_in,
                              void* d_out, int out_size)
{
    const float* x      = (const float*)d_in[0];
    const float* w_qkv  = (const float*)d_in[1];
    const float* w_proj = (const float*)d_in[2];
    const float* b_proj = (const float*)d_in[3];
    float* out = (float*)d_out;

    float *p_q, *p_k, *p_v;
    __half *p_xhi, *p_xlo, *p_wqkv, *p_wproj, *p_wf;
    cudaGetSymbolAddress((void**)&p_q, g_q);
    cudaGetSymbolAddress((void**)&p_k, g_k);
    cudaGetSymbolAddress((void**)&p_v, g_v);
    cudaGetSymbolAddress((void**)&p_xhi, g_xhi);
    cudaGetSymbolAddress((void**)&p_xlo, g_xlo);
    cudaGetSymbolAddress((void**)&p_wqkv, g_wqkv);
    cudaGetSymbolAddress((void**)&p_wproj, g_wproj);
    cudaGetSymbolAddress((void**)&p_wf, g_wf);

    const int GSMEM3 = 2 * 3 * TILE_B;   // 61440
    const int GSMEM2 = 2 * 2 * TILE_B;   // 40960
    cudaFuncSetAttribute(tgemm_k<true>,  cudaFuncAttributeMaxDynamicSharedMemorySize, GSMEM3);
    cudaFuncSetAttribute(tgemm_k<false>, cudaFuncAttributeMaxDynamicSharedMemorySize, GSMEM2);
    cudaFuncSetAttribute(attn_spatial_k, cudaFuncAttributeMaxDynamicSharedMemorySize, ATSMEM);

    // 0) fp16 conversions
    cvt_split_h<<<(unsigned)((MD_ELEMS + 255) / 256), 256>>>(x, p_xhi, p_xlo, MD_ELEMS);
    cvt_h<<<(unsigned)(((size_t)E3 * Ddim + 255) / 256), 256>>>(
        w_qkv, p_wqkv, (size_t)E3 * Ddim);
    cvt_h<<<(unsigned)(((size_t)Ddim * Ddim + 255) / 256), 256>>>(
        w_proj, p_wproj, (size_t)Ddim * Ddim);

    // 1) qkv GEMM (2-pass) with fused scatter into q/k/v head layout
    tgemm_k<true><<<dim3(E3 / 128, Mrows / 128), 256, GSMEM3>>>(
        p_xhi, p_xlo, p_wqkv, nullptr, nullptr, E3, 0, p_q, p_k, p_v);

    // 2) MMA flash spatial attention (fp16)
    attn_spatial_k<<<768, AT_T, ATSMEM>>>();

    // 3) temporal attention
    attn_temporal_k<<<(Bdim * 6 * Ndim) / 128, 128>>>();

    // 4) out = wf @ w_proj^T + b_proj (1-pass)
    tgemm_k<false><<<dim3(Ddim / 128, Mrows / 128), 256, GSMEM2>>>(
        p_wf, nullptr, p_wproj, b_proj, out, Ddim, 1,
        nullptr, nullptr, nullptr);
}

// round 14
// speedup vs baseline: 2.6500x; 1.3066x over previous
#include <cuda_runtime.h>
#include <cuda_fp16.h>
#include <cstdint>
#include <cstddef>

// ---------------------------------------------------------------------------
// Problem constants
// ---------------------------------------------------------------------------
#define Bdim  8
#define Fdim  16
#define Pdim  196
#define Ddim  768
#define Hh    12
#define HD    64
#define Ndim  3136              // F*P
#define Mrows 25088             // B*N
#define E3    2304              // 3*D

#define HEAD_ELEMS ((size_t)Bdim * Hh * Ndim * HD)
#define MD_ELEMS   ((size_t)Mrows * Ddim)

// Scratch (__device__ globals; allocation-free rule)
__device__ float g_q[HEAD_ELEMS];
__device__ float g_k[HEAD_ELEMS];
__device__ float g_v[HEAD_ELEMS];

__device__ __half g_x[MD_ELEMS];
__device__ __half g_wqkv[(size_t)E3 * Ddim];
__device__ __half g_wproj[(size_t)Ddim * Ddim];
__device__ __half g_wf[MD_ELEMS];

// ---------------------------------------------------------------------------
// helpers
// ---------------------------------------------------------------------------
__device__ __forceinline__ void cp_async16(uint32_t dst, const void* src) {
    asm volatile("cp.async.cg.shared.global [%0], [%1], 16;"
                 :: "r"(dst), "l"(src) : "memory");
}
#define CP_COMMIT() asm volatile("cp.async.commit_group;" ::: "memory")
template <int N> __device__ __forceinline__ void cp_wait() {
    asm volatile("cp.async.wait_group %0;" :: "n"(N) : "memory");
}
__device__ __forceinline__ uint32_t smem_u32(const void* p) {
    uint32_t a;
    asm("{ .reg .u64 t; cvta.to.shared.u64 t, %1; cvt.u32.u64 %0, t; }"
        : "=r"(a) : "l"(p));
    return a;
}

// fp16 mma
__device__ __forceinline__ void mma16816h(float* d,
                                          uint32_t a0, uint32_t a1, uint32_t a2, uint32_t a3,
                                          uint32_t b0, uint32_t b1) {
    asm volatile(
        "mma.sync.aligned.m16n8k16.row.col.f32.f16.f16.f32 "
        "{%0,%1,%2,%3}, {%4,%5,%6,%7}, {%8,%9}, {%0,%1,%2,%3};"
        : "+f"(d[0]), "+f"(d[1]), "+f"(d[2]), "+f"(d[3])
        : "r"(a0), "r"(a1), "r"(a2), "r"(a3), "r"(b0), "r"(b1));
}

__device__ __forceinline__ void ldsm4(uint32_t& r0, uint32_t& r1,
                                      uint32_t& r2, uint32_t& r3, uint32_t addr) {
    asm volatile("ldmatrix.sync.aligned.m8n8.x4.shared.b16 {%0,%1,%2,%3}, [%4];"
                 : "=r"(r0), "=r"(r1), "=r"(r2), "=r"(r3) : "r"(addr));
}

__device__ __forceinline__ uint32_t pack_h2(float x, float y) {
    __half2 t = __floats2half2_rn(x, y);
    return *(uint32_t*)&t;
}

// ---------------------------------------------------------------------------
// HMMA GEMM (fp16, single-pass):  C = A[M,768] * B[N,768]^T
// 128x128x32 CTA tile, 256 threads, warp grid 2(M)x4(N), warp tile 64x32.
// LDK=40 (80B rows, conflict-free ldmatrix), 2-stage cp.async, single sync.
// mode 0: scatter epilogue into q/k/v head layout; mode 1: C + bias.
// ---------------------------------------------------------------------------
#define BK       32
#define LDK      40
#define TILE_B   (128 * LDK * 2)          // 10240
#define STAGE_B  (2 * TILE_B)             // 20480 (A, B)
#define GSMEM    (2 * STAGE_B)            // 40960
#define OFF_B    TILE_B

__global__ __launch_bounds__(256, 2) void tgemm_k(
    const __half* __restrict__ Am, const __half* __restrict__ Bm,
    const float* __restrict__ bias, float* __restrict__ C, int Nd, int mode,
    float* __restrict__ Qo, float* __restrict__ Ko, float* __restrict__ Vo)
{
    extern __shared__ char smem[];
    const uint32_t sb = smem_u32(smem);

    const int tid  = threadIdx.x;
    const int lane = tid & 31;
    const int wid  = tid >> 5;
    const int wm   = wid & 1;
    const int wn   = wid >> 1;
    const int g    = lane >> 2;
    const int tg   = lane & 3;

    const int bm = blockIdx.y * 128;
    const int bn = blockIdx.x * 128;

    const int a_row = wm * 64 + (lane & 15);
    const int a_kc  = (lane >> 4) * 8;
    const int b_row = wn * 32 + ((lane >> 4) << 3) + (lane & 7);
    const int b_kc  = ((lane >> 3) & 1) * 8;

    auto load_chunk = [&](int k0, int stage) {
        const uint32_t dbase = sb + stage * STAGE_B;
#pragma unroll
        for (int j = 0; j < 4; j++) {
            const int tile = j >> 1;                 // 0:A 1:B
            const int within = tid + (j & 1) * 256;  // 0..511
            const int row = within >> 2;
            const int gr  = within & 3;
            const __half* srcb = (tile == 0) ? Am : Bm;
            const int rowb = (tile == 0) ? bm : bn;
            const void* src = srcb + (size_t)(rowb + row) * Ddim + k0 + gr * 8;
            cp_async16(dbase + (uint32_t)(tile * TILE_B + row * (LDK * 2) + gr * 16), src);
        }
        CP_COMMIT();
    };

    float acc[4][4][4];
#pragma unroll
    for (int i = 0; i < 4; i++)
#pragma unroll
        for (int j = 0; j < 4; j++)
#pragma unroll
            for (int q = 0; q < 4; q++) acc[i][j][q] = 0.f;

    load_chunk(0, 0);

    const int NCH = Ddim / BK;   // 24
    for (int c = 0; c < NCH; c++) {
        cp_wait<0>();
        __syncthreads();
        if (c + 1 < NCH) load_chunk((c + 1) * BK, (c + 1) & 1);

        const uint32_t st = sb + (c & 1) * STAGE_B;

#pragma unroll
        for (int ks = 0; ks < 2; ks++) {
            const int kcA = ks * 16 + a_kc;
            const int kcB = ks * 16 + b_kc;
            uint32_t ah[4][4];
#pragma unroll
            for (int mt = 0; mt < 4; mt++) {
                uint32_t addr = st + (uint32_t)(((a_row + mt * 16) * LDK + kcA) * 2);
                ldsm4(ah[mt][0], ah[mt][1], ah[mt][2], ah[mt][3], addr);
            }
#pragma unroll
            for (int p = 0; p < 2; p++) {
                uint32_t baddr = st + (uint32_t)(((b_row + p * 16) * LDK + kcB) * 2);
                uint32_t bh[2][2];
                ldsm4(bh[0][0], bh[0][1], bh[1][0], bh[1][1], baddr + OFF_B);
#pragma unroll
                for (int q = 0; q < 2; q++) {
                    const int nt = p * 2 + q;
#pragma unroll
                    for (int mt = 0; mt < 4; mt++) {
                        mma16816h(acc[mt][nt], ah[mt][0], ah[mt][1], ah[mt][2], ah[mt][3],
                                  bh[q][0], bh[q][1]);
                    }
                }
            }
        }
    }

    if (mode == 1) {
#pragma unroll
        for (int mt = 0; mt < 4; mt++) {
            int r0 = bm + wm * 64 + mt * 16 + g;
#pragma unroll
            for (int nt = 0; nt < 4; nt++) {
                int c0 = bn + wn * 32 + nt * 8 + tg * 2;
                float b0 = bias[c0], b1 = bias[c0 + 1];
                float2 v0 = make_float2(acc[mt][nt][0] + b0, acc[mt][nt][1] + b1);
                float2 v1 = make_float2(acc[mt][nt][2] + b0, acc[mt][nt][3] + b1);
                *(float2*)(C + (size_t)r0 * Nd + c0) = v0;
                *(float2*)(C + (size_t)(r0 + 8) * Nd + c0) = v1;
            }
        }
    } else {
#pragma unroll
        for (int nt = 0; nt < 4; nt++) {
            int c0 = bn + wn * 32 + nt * 8 + tg * 2;
            int t = c0 / Ddim;
            int rem = c0 - t * Ddim;
            int h = rem >> 6, d = rem & 63;
            float* dst = (t == 0) ? Qo : (t == 1) ? Ko : Vo;
#pragma unroll
            for (int mt = 0; mt < 4; mt++) {
                int r0 = bm + wm * 64 + mt * 16 + g;
#pragma unroll
                for (int rr = 0; rr < 2; rr++) {
                    int r = r0 + rr * 8;
                    int b = r / Ndim;
                    int n = r - b * Ndim;
                    size_t off = (((size_t)(b * Hh + h)) * Ndim + n) * HD + d;
                    float2 v = make_float2(acc[mt][nt][2 * rr], acc[mt][nt][2 * rr + 1]);
                    *(float2*)(dst + off) = v;
                }
            }
        }
    }
}

// ---------------------------------------------------------------------------
// fp32 -> fp16
// ---------------------------------------------------------------------------
__global__ void cvt_h(const float* __restrict__ in, __half* __restrict__ out, size_t n)
{
    size_t i = (size_t)blockIdx.x * 256 + threadIdx.x;
    if (i >= n) return;
    out[i] = __float2half(in[i]);
}

// ---------------------------------------------------------------------------
// MMA flash spatial attention (fp16): 768 groups (heads 0..5), 196x196, d=64.
// Q split hi/lo (2-pass S vs single K); P split hi/lo (2-pass PV vs single
// V^T). 13 warps; warp = one 16-row m-tile. Output -> g_wf (single fp16).
// ---------------------------------------------------------------------------
#define AT_T    416
#define MPAD    208
#define LDA     72
#define OQH     0
#define OQL     (MPAD * LDA * 2)          // 29952
#define OKH     (2 * MPAD * LDA * 2)      // 59904
#define OVH     (OKH + 64 * LDA * 2)      // 69120
#define ATSMEM  (OVH + 64 * LDA * 2)      // 78336

__global__ __launch_bounds__(AT_T, 1) void attn_spatial_k()
{
    extern __shared__ char smem[];
    const uint32_t sb = smem_u32(smem);
    __half* Qhi = (__half*)(smem + OQH);
    __half* Qlo = (__half*)(smem + OQL);
    __half* Ks  = (__half*)(smem + OKH);
    __half* Vt  = (__half*)(smem + OVH);

    const int grp = blockIdx.x;
    const int b = grp / 96;
    const int h = (grp % 96) / 16;
    const int f = grp % 16;
    const size_t base = (((size_t)(b * Hh + h)) * Ndim + f * Pdim) * HD;

    const int tid  = threadIdx.x;
    const int lane = tid & 31;
    const int wid  = tid >> 5;
    const int gq   = lane >> 2;
    const int tg   = lane & 3;

    for (int idx = tid; idx < MPAD * 64; idx += AT_T) {
        int r = idx >> 6, c = idx & 63;
        float v = (r < Pdim) ? g_q[base + (size_t)r * HD + c] : 0.f;
        __half hv = __float2half(v);
        Qhi[r * LDA + c] = hv;
        Qlo[r * LDA + c] = __float2half(v - __half2float(hv));
    }
    __syncthreads();

    uint32_t qh[4][4], ql[4][4];
    {
        const int arow = wid * 16 + (lane & 15);
        const int acol = (lane >> 4) * 8;
#pragma unroll
        for (int kb = 0; kb < 4; kb++) {
            uint32_t addr = sb + (uint32_t)((arow * LDA + kb * 16 + acol) * 2);
            ldsm4(qh[kb][0], qh[kb][1], qh[kb][2], qh[kb][3], addr + OQH);
            ldsm4(ql[kb][0], ql[kb][1], ql[kb][2], ql[kb][3], addr + OQL);
        }
    }

    float ofr[8][4];
#pragma unroll
    for (int j = 0; j < 8; j++)
#pragma unroll
        for (int q = 0; q < 4; q++) ofr[j][q] = 0.f;
    float mx0 = -1e30f, mx1 = -1e30f, ls0 = 0.f, ls1 = 0.f;
    const float scale = 0.125f;

    const int brow = ((lane >> 4) << 3) + (lane & 7);
    const int bcol = ((lane >> 3) & 1) * 8;

    for (int ch = 0; ch < 4; ch++) {
        __syncthreads();
        const int kbase = ch * 64;
        for (int idx = tid; idx < 64 * 64; idx += AT_T) {
            int r = idx >> 6, c = idx & 63;
            int key = kbase + r;
            float kv = (key < Pdim) ? g_k[base + (size_t)key * HD + c] : 0.f;
            Ks[r * LDA + c] = __float2half(kv);
            float vv = (key < Pdim) ? g_v[base + (size_t)key * HD + c] : 0.f;
            Vt[c * LDA + r] = __float2half(vv);
        }
        __syncthreads();

        float sfr[8][4];
#pragma unroll
        for (int j = 0; j < 8; j++)
#pragma unroll
            for (int q = 0; q < 4; q++) sfr[j][q] = 0.f;

#pragma unroll
        for (int kb = 0; kb < 4; kb++) {
#pragma unroll
            for (int p = 0; p < 4; p++) {
                uint32_t ka = sb + (uint32_t)(((p * 16 + brow) * LDA + kb * 16 + bcol) * 2);
                uint32_t bh0, bh1, bh2, bh3;
                ldsm4(bh0, bh1, bh2, bh3, ka + OKH);
                mma16816h(sfr[2 * p], qh[kb][0], qh[kb][1], qh[kb][2], qh[kb][3], bh0, bh1);
                mma16816h(sfr[2 * p], ql[kb][0], ql[kb][1], ql[kb][2], ql[kb][3], bh0, bh1);
                mma16816h(sfr[2 * p + 1], qh[kb][0], qh[kb][1], qh[kb][2], qh[kb][3], bh2, bh3);
                mma16816h(sfr[2 * p + 1], ql[kb][0], ql[kb][1], ql[kb][2], ql[kb][3], bh2, bh3);
            }
        }

        const int nvalid = Pdim - kbase;
#pragma unroll
        for (int j = 0; j < 8; j++)
#pragma unroll
            for (int q = 0; q < 4; q++) {
                int key = j * 8 + 2 * tg + (q & 1);
                sfr[j][q] = (key < nvalid) ? sfr[j][q] * scale : -1e30f;
            }

        float rm0 = -1e30f, rm1 = -1e30f;
#pragma unroll
        for (int j = 0; j < 8; j++) {
            rm0 = fmaxf(rm0, fmaxf(sfr[j][0], sfr[j][1]));
            rm1 = fmaxf(rm1, fmaxf(sfr[j][2], sfr[j][3]));
        }
        rm0 = fmaxf(rm0, __shfl_xor_sync(0xFFFFFFFFu, rm0, 1));
        rm0 = fmaxf(rm0, __shfl_xor_sync(0xFFFFFFFFu, rm0, 2));
        rm1 = fmaxf(rm1, __shfl_xor_sync(0xFFFFFFFFu, rm1, 1));
        rm1 = fmaxf(rm1, __shfl_xor_sync(0xFFFFFFFFu, rm1, 2));
        float nm0 = fmaxf(mx0, rm0), nm1 = fmaxf(mx1, rm1);
        float c0 = __expf(mx0 - nm0), c1 = __expf(mx1 - nm1);
        mx0 = nm0; mx1 = nm1;
        ls0 *= c0; ls1 *= c1;
#pragma unroll
        for (int j = 0; j < 8; j++) {
            ofr[j][0] *= c0; ofr[j][1] *= c0;
            ofr[j][2] *= c1; ofr[j][3] *= c1;
        }

        float rs0 = 0.f, rs1 = 0.f;
#pragma unroll
        for (int j = 0; j < 8; j++) {
            float p0 = __expf(sfr[j][0] - nm0);
            float p1 = __expf(sfr[j][1] - nm0);
            float p2 = __expf(sfr[j][2] - nm1);
            float p3 = __expf(sfr[j][3] - nm1);
            rs0 += p0 + p1; rs1 += p2 + p3;
            sfr[j][0] = p0; sfr[j][1] = p1; sfr[j][2] = p2; sfr[j][3] = p3;
        }
        rs0 += __shfl_xor_sync(0xFFFFFFFFu, rs0, 1);
        rs0 += __shfl_xor_sync(0xFFFFFFFFu, rs0, 2);
        rs1 += __shfl_xor_sync(0xFFFFFFFFu, rs1, 1);
        rs1 += __shfl_xor_sync(0xFFFFFFFFu, rs1, 2);
        ls0 += rs0; ls1 += rs1;

#pragma unroll
        for (int kb = 0; kb < 4; kb++) {
            uint32_t pah[4], pal[4];
#pragma unroll
            for (int half = 0; half < 2; half++) {
                const int j = 2 * kb + half;
                float p0 = sfr[j][0], p1 = sfr[j][1], p2 = sfr[j][2], p3 = sfr[j][3];
                __half h0 = __float2half(p0);
                __half h1 = __float2half(p1);
                __half h2 = __float2half(p2);
                __half h3 = __float2half(p3);
                pah[2 * half + 0] = pack_h2(__half2float(h0), __half2float(h1));
                pah[2 * half + 1] = pack_h2(__half2float(h2), __half2float(h3));
                pal[2 * half + 0] = pack_h2(p0 - __half2float(h0), p1 - __half2float(h1));
                pal[2 * half + 1] = pack_h2(p2 - __half2float(h2), p3 - __half2float(h3));
            }
#pragma unroll
            for (int p = 0; p < 4; p++) {
                uint32_t va = sb + (uint32_t)(((p * 16 + brow) * LDA + kb * 16 + bcol) * 2);
                uint32_t vh0, vh1, vh2, vh3;
                ldsm4(vh0, vh1, vh2, vh3, va + OVH);
                mma16816h(ofr[2 * p], pah[0], pah[1], pah[2], pah[3], vh0, vh1);
                mma16816h(ofr[2 * p], pal[0], pal[1], pal[2], pal[3], vh0, vh1);
                mma16816h(ofr[2 * p + 1], pah[0], pah[1], pah[2], pah[3], vh2, vh3);
                mma16816h(ofr[2 * p + 1], pal[0], pal[1], pal[2], pal[3], vh2, vh3);
            }
        }
    }

    float inv0 = 1.f / ls0, inv1 = 1.f / ls1;
    const int r0 = wid * 16 + gq;
    const int r1 = r0 + 8;
    if (r0 < Pdim) {
        const size_t ob = ((size_t)b * Ndim + (f * Pdim + r0)) * Ddim + h * HD;
#pragma unroll
        for (int j = 0; j < 8; j++) {
            __half2 hv = __floats2half2_rn(ofr[j][0] * inv0, ofr[j][1] * inv0);
            *(__half2*)(g_wf + ob + j * 8 + 2 * tg) = hv;
        }
    }
    if (r1 < Pdim) {
        const size_t ob = ((size_t)b * Ndim + (f * Pdim + r1)) * Ddim + h * HD;
#pragma unroll
        for (int j = 0; j < 8; j++) {
            __half2 hv = __floats2half2_rn(ofr[j][2] * inv1, ofr[j][3] * inv1);
            *(__half2*)(g_wf + ob + j * 8 + 2 * tg) = hv;
        }
    }
}

// ---------------------------------------------------------------------------
// Temporal attention: heads 6..11, groups of 16 rows. Writes g_wf (fp16).
// ---------------------------------------------------------------------------
__global__ __launch_bounds__(128) void attn_temporal_k()
{
    int tid = blockIdx.x * 128 + threadIdx.x;
    const int TOT = Bdim * 6 * Ndim;
    if (tid >= TOT) return;
    int b = tid / (6 * Ndim);
    int rr = tid - b * (6 * Ndim);
    int h = 6 + rr / Ndim;
    int n = rr % Ndim;
    int n0 = n & ~15;
    size_t row = (((size_t)(b * Hh + h)) * Ndim + n) * HD;
    size_t gb  = (((size_t)(b * Hh + h)) * Ndim + n0) * HD;

    float4 q4[16];
    const float4* qp = (const float4*)(g_q + row);
#pragma unroll
    for (int i = 0; i < 16; i++) q4[i] = qp[i];

    float s[16];
    float mx = -1e30f;
#pragma unroll
    for (int f = 0; f < 16; f++) {
        const float4* kp = (const float4*)(g_k + gb + (size_t)f * HD);
        float a = 0.f;
#pragma unroll
        for (int i = 0; i < 16; i++) {
            float4 kv = kp[i];
            a = fmaf(q4[i].x, kv.x, a);
            a = fmaf(q4[i].y, kv.y, a);
            a = fmaf(q4[i].z, kv.z, a);
            a = fmaf(q4[i].w, kv.w, a);
        }
        s[f] = a * 0.125f;
        mx = fmaxf(mx, s[f]);
    }
    float lsum = 0.f;
#pragma unroll
    for (int f = 0; f < 16; f++) { s[f] = __expf(s[f] - mx); lsum += s[f]; }
    float inv = 1.f / lsum;
#pragma unroll
    for (int f = 0; f < 16; f++) s[f] *= inv;

    const size_t obase = ((size_t)b * Ndim + n) * Ddim + h * HD;
#pragma unroll
    for (int ch = 0; ch < 4; ch++) {
        float4 a4[4];
#pragma unroll
        for (int i = 0; i < 4; i++) a4[i] = make_float4(0.f, 0.f, 0.f, 0.f);
#pragma unroll
        for (int f = 0; f < 16; f++) {
            float p = s[f];
            const float4* vp = (const float4*)(g_v + gb + (size_t)f * HD + ch * 16);
#pragma unroll
            for (int i = 0; i < 4; i++) {
                float4 vv = vp[i];
                a4[i].x = fmaf(p, vv.x, a4[i].x);
                a4[i].y = fmaf(p, vv.y, a4[i].y);
                a4[i].z = fmaf(p, vv.z, a4[i].z);
                a4[i].w = fmaf(p, vv.w, a4[i].w);
            }
        }
#pragma unroll
        for (int i = 0; i < 4; i++) {
            __half2 h0 = __floats2half2_rn(a4[i].x, a4[i].y);
            __half2 h1 = __floats2half2_rn(a4[i].z, a4[i].w);
            size_t o = obase + ch * 16 + i * 4;
            *(__half2*)(g_wf + o) = h0;
            *(__half2*)(g_wf + o + 2) = h1;
        }
    }
}

// ---------------------------------------------------------------------------
// Launch
// ---------------------------------------------------------------------------
extern "C" void kernel_launch(void* const* d_in, const int* in_sizes, int n_in,
                              void* d_out, int out_size)
{
    const float* x      = (const float*)d_in[0];
    const float* w_qkv  = (const float*)d_in[1];
    const float* w_proj = (const float*)d_in[2];
    const float* b_proj = (const float*)d_in[3];
    float* out = (float*)d_out;

    float *p_q, *p_k, *p_v;
    __half *p_x, *p_wqkv, *p_wproj, *p_wf;
    cudaGetSymbolAddress((void**)&p_q, g_q);
    cudaGetSymbolAddress((void**)&p_k, g_k);
    cudaGetSymbolAddress((void**)&p_v, g_v);
    cudaGetSymbolAddress((void**)&p_x, g_x);
    cudaGetSymbolAddress((void**)&p_wqkv, g_wqkv);
    cudaGetSymbolAddress((void**)&p_wproj, g_wproj);
    cudaGetSymbolAddress((void**)&p_wf, g_wf);

    cudaFuncSetAttribute(tgemm_k, cudaFuncAttributeMaxDynamicSharedMemorySize, GSMEM);
    cudaFuncSetAttribute(attn_spatial_k, cudaFuncAttributeMaxDynamicSharedMemorySize, ATSMEM);

    // 0) fp16 conversions (all single-rounded)
    cvt_h<<<(unsigned)((MD_ELEMS + 255) / 256), 256>>>(x, p_x, MD_ELEMS);
    cvt_h<<<(unsigned)(((size_t)E3 * Ddim + 255) / 256), 256>>>(
        w_qkv, p_wqkv, (size_t)E3 * Ddim);
    cvt_h<<<(unsigned)(((size_t)Ddim * Ddim + 255) / 256), 256>>>(
        w_proj, p_wproj, (size_t)Ddim * Ddim);

    // 1) qkv GEMM (1-pass) with fused scatter into q/k/v head layout
    tgemm_k<<<dim3(E3 / 128, Mrows / 128), 256, GSMEM>>>(
        p_x, p_wqkv, nullptr, nullptr, E3, 0, p_q, p_k, p_v);

    // 2) MMA flash spatial attention (fp16)
    attn_spatial_k<<<768, AT_T, ATSMEM>>>();

    // 3) temporal attention
    attn_temporal_k<<<(Bdim * 6 * Ndim) / 128, 128>>>();

    // 4) out = wf @ w_proj^T + b_proj (1-pass)
    tgemm_k<<<dim3(Ddim / 128, Mrows / 128), 256, GSMEM>>>(
        p_wf, p_wproj, b_proj, out, Ddim, 1, nullptr, nullptr, nullptr);
}

// round 15
// speedup vs baseline: 2.9511x; 1.1136x over previous
#include <cuda_runtime.h>
#include <cuda_fp16.h>
#include <cstdint>
#include <cstddef>

// ---------------------------------------------------------------------------
// Problem constants
// ---------------------------------------------------------------------------
#define Bdim  8
#define Fdim  16
#define Pdim  196
#define Ddim  768
#define Hh    12
#define HD    64
#define Ndim  3136              // F*P
#define Mrows 25088             // B*N
#define E3    2304              // 3*D

#define HEAD_ELEMS ((size_t)Bdim * Hh * Ndim * HD)
#define MD_ELEMS   ((size_t)Mrows * Ddim)

// Scratch (__device__ globals; allocation-free rule)
__device__ __half g_q[HEAD_ELEMS];
__device__ __half g_k[HEAD_ELEMS];
__device__ __half g_v[HEAD_ELEMS];

__device__ __half g_x[MD_ELEMS];
__device__ __half g_wqkv[(size_t)E3 * Ddim];
__device__ __half g_wproj[(size_t)Ddim * Ddim];
__device__ __half g_wf[MD_ELEMS];

// ---------------------------------------------------------------------------
// helpers
// ---------------------------------------------------------------------------
__device__ __forceinline__ void cp_async16(uint32_t dst, const void* src) {
    asm volatile("cp.async.cg.shared.global [%0], [%1], 16;"
                 :: "r"(dst), "l"(src) : "memory");
}
#define CP_COMMIT() asm volatile("cp.async.commit_group;" ::: "memory")
template <int N> __device__ __forceinline__ void cp_wait() {
    asm volatile("cp.async.wait_group %0;" :: "n"(N) : "memory");
}
__device__ __forceinline__ uint32_t smem_u32(const void* p) {
    uint32_t a;
    asm("{ .reg .u64 t; cvta.to.shared.u64 t, %1; cvt.u32.u64 %0, t; }"
        : "=r"(a) : "l"(p));
    return a;
}

// fp16 mma
__device__ __forceinline__ void mma16816h(float* d,
                                          uint32_t a0, uint32_t a1, uint32_t a2, uint32_t a3,
                                          uint32_t b0, uint32_t b1) {
    asm volatile(
        "mma.sync.aligned.m16n8k16.row.col.f32.f16.f16.f32 "
        "{%0,%1,%2,%3}, {%4,%5,%6,%7}, {%8,%9}, {%0,%1,%2,%3};"
        : "+f"(d[0]), "+f"(d[1]), "+f"(d[2]), "+f"(d[3])
        : "r"(a0), "r"(a1), "r"(a2), "r"(a3), "r"(b0), "r"(b1));
}

__device__ __forceinline__ void ldsm4(uint32_t& r0, uint32_t& r1,
                                      uint32_t& r2, uint32_t& r3, uint32_t addr) {
    asm volatile("ldmatrix.sync.aligned.m8n8.x4.shared.b16 {%0,%1,%2,%3}, [%4];"
                 : "=r"(r0), "=r"(r1), "=r"(r2), "=r"(r3) : "r"(addr));
}

__device__ __forceinline__ uint32_t pack_h2(float x, float y) {
    __half2 t = __floats2half2_rn(x, y);
    return *(uint32_t*)&t;
}

// ---------------------------------------------------------------------------
// HMMA GEMM (fp16, single-pass):  C = A[M,768] * B[N,768]^T
// 128x128x32 CTA tile, 256 threads, warp grid 2(M)x4(N), warp tile 64x32.
// LDK=40 (80B rows, conflict-free ldmatrix), 2-stage cp.async, single sync.
// mode 0: scatter epilogue into fp16 q/k/v head layout; mode 1: C + bias.
// ---------------------------------------------------------------------------
#define BK       32
#define LDK      40
#define TILE_B   (128 * LDK * 2)          // 10240
#define STAGE_B  (2 * TILE_B)             // 20480 (A, B)
#define GSMEM    (2 * STAGE_B)            // 40960
#define OFF_B    TILE_B

__global__ __launch_bounds__(256, 2) void tgemm_k(
    const __half* __restrict__ Am, const __half* __restrict__ Bm,
    const float* __restrict__ bias, float* __restrict__ C, int Nd, int mode,
    __half* __restrict__ Qo, __half* __restrict__ Ko, __half* __restrict__ Vo)
{
    extern __shared__ char smem[];
    const uint32_t sb = smem_u32(smem);

    const int tid  = threadIdx.x;
    const int lane = tid & 31;
    const int wid  = tid >> 5;
    const int wm   = wid & 1;
    const int wn   = wid >> 1;
    const int g    = lane >> 2;
    const int tg   = lane & 3;

    const int bm = blockIdx.y * 128;
    const int bn = blockIdx.x * 128;

    const int a_row = wm * 64 + (lane & 15);
    const int a_kc  = (lane >> 4) * 8;
    const int b_row = wn * 32 + ((lane >> 4) << 3) + (lane & 7);
    const int b_kc  = ((lane >> 3) & 1) * 8;

    auto load_chunk = [&](int k0, int stage) {
        const uint32_t dbase = sb + stage * STAGE_B;
#pragma unroll
        for (int j = 0; j < 4; j++) {
            const int tile = j >> 1;                 // 0:A 1:B
            const int within = tid + (j & 1) * 256;  // 0..511
            const int row = within >> 2;
            const int gr  = within & 3;
            const __half* srcb = (tile == 0) ? Am : Bm;
            const int rowb = (tile == 0) ? bm : bn;
            const void* src = srcb + (size_t)(rowb + row) * Ddim + k0 + gr * 8;
            cp_async16(dbase + (uint32_t)(tile * TILE_B + row * (LDK * 2) + gr * 16), src);
        }
        CP_COMMIT();
    };

    float acc[4][4][4];
#pragma unroll
    for (int i = 0; i < 4; i++)
#pragma unroll
        for (int j = 0; j < 4; j++)
#pragma unroll
            for (int q = 0; q < 4; q++) acc[i][j][q] = 0.f;

    load_chunk(0, 0);

    const int NCH = Ddim / BK;   // 24
    for (int c = 0; c < NCH; c++) {
        cp_wait<0>();
        __syncthreads();
        if (c + 1 < NCH) load_chunk((c + 1) * BK, (c + 1) & 1);

        const uint32_t st = sb + (c & 1) * STAGE_B;

#pragma unroll
        for (int ks = 0; ks < 2; ks++) {
            const int kcA = ks * 16 + a_kc;
            const int kcB = ks * 16 + b_kc;
            uint32_t ah[4][4];
#pragma unroll
            for (int mt = 0; mt < 4; mt++) {
                uint32_t addr = st + (uint32_t)(((a_row + mt * 16) * LDK + kcA) * 2);
                ldsm4(ah[mt][0], ah[mt][1], ah[mt][2], ah[mt][3], addr);
            }
#pragma unroll
            for (int p = 0; p < 2; p++) {
                uint32_t baddr = st + (uint32_t)(((b_row + p * 16) * LDK + kcB) * 2);
                uint32_t bh[2][2];
                ldsm4(bh[0][0], bh[0][1], bh[1][0], bh[1][1], baddr + OFF_B);
#pragma unroll
                for (int q = 0; q < 2; q++) {
                    const int nt = p * 2 + q;
#pragma unroll
                    for (int mt = 0; mt < 4; mt++) {
                        mma16816h(acc[mt][nt], ah[mt][0], ah[mt][1], ah[mt][2], ah[mt][3],
                                  bh[q][0], bh[q][1]);
                    }
                }
            }
        }
    }

    if (mode == 1) {
#pragma unroll
        for (int mt = 0; mt < 4; mt++) {
            int r0 = bm + wm * 64 + mt * 16 + g;
#pragma unroll
            for (int nt = 0; nt < 4; nt++) {
                int c0 = bn + wn * 32 + nt * 8 + tg * 2;
                float b0 = bias[c0], b1 = bias[c0 + 1];
                float2 v0 = make_float2(acc[mt][nt][0] + b0, acc[mt][nt][1] + b1);
                float2 v1 = make_float2(acc[mt][nt][2] + b0, acc[mt][nt][3] + b1);
                *(float2*)(C + (size_t)r0 * Nd + c0) = v0;
                *(float2*)(C + (size_t)(r0 + 8) * Nd + c0) = v1;
            }
        }
    } else {
        // scatter into fp16 q/k/v (B,12,N,64) head layout
#pragma unroll
        for (int nt = 0; nt < 4; nt++) {
            int c0 = bn + wn * 32 + nt * 8 + tg * 2;
            int t = c0 / Ddim;
            int rem = c0 - t * Ddim;
            int h = rem >> 6, d = rem & 63;
            __half* dst = (t == 0) ? Qo : (t == 1) ? Ko : Vo;
#pragma unroll
            for (int mt = 0; mt < 4; mt++) {
                int r0 = bm + wm * 64 + mt * 16 + g;
#pragma unroll
                for (int rr = 0; rr < 2; rr++) {
                    int r = r0 + rr * 8;
                    int b = r / Ndim;
                    int n = r - b * Ndim;
                    size_t off = (((size_t)(b * Hh + h)) * Ndim + n) * HD + d;
                    __half2 hv = __floats2half2_rn(acc[mt][nt][2 * rr], acc[mt][nt][2 * rr + 1]);
                    *(__half2*)(dst + off) = hv;
                }
            }
        }
    }
}

// ---------------------------------------------------------------------------
// fp32 -> fp16
// ---------------------------------------------------------------------------
__global__ void cvt_h(const float* __restrict__ in, __half* __restrict__ out, size_t n)
{
    size_t i = (size_t)blockIdx.x * 256 + threadIdx.x;
    if (i >= n) return;
    out[i] = __float2half(in[i]);
}

// ---------------------------------------------------------------------------
// MMA flash spatial attention (fp16): 768 groups (heads 0..5), 196x196, d=64.
// q/k/v already fp16 -> single-pass S (no Q split). P split hi/lo 2-pass PV.
// 13 warps; warp = one 16-row m-tile. Output -> g_wf (single fp16).
// ---------------------------------------------------------------------------
#define AT_T    416
#define MPAD    208
#define LDA     72
#define OQ      0
#define OK      (MPAD * LDA * 2)          // 29952
#define OV      (OK + 64 * LDA * 2)       // 39168
#define ATSMEM  (OV + 64 * LDA * 2)       // 48384

__global__ __launch_bounds__(AT_T, 1) void attn_spatial_k()
{
    extern __shared__ char smem[];
    const uint32_t sb = smem_u32(smem);
    __half* Qs = (__half*)(smem + OQ);
    __half* Ks = (__half*)(smem + OK);
    __half* Vt = (__half*)(smem + OV);

    const int grp = blockIdx.x;
    const int b = grp / 96;
    const int h = (grp % 96) / 16;
    const int f = grp % 16;
    const size_t base = (((size_t)(b * Hh + h)) * Ndim + f * Pdim) * HD;

    const int tid  = threadIdx.x;
    const int lane = tid & 31;
    const int wid  = tid >> 5;
    const int gq   = lane >> 2;
    const int tg   = lane & 3;

    // fill Q: 16B granules (8 halves), zero-pad rows >= 196
    {
        const uint4 z = make_uint4(0, 0, 0, 0);
        for (int idx = tid; idx < MPAD * 8; idx += AT_T) {
            int r = idx >> 3, c8 = (idx & 7) * 8;
            uint4 u = (r < Pdim) ? *(const uint4*)(g_q + base + (size_t)r * HD + c8) : z;
            *(uint4*)(Qs + r * LDA + c8) = u;
        }
    }
    __syncthreads();

    // Q fragments (A-operand), loaded once
    uint32_t qh[4][4];
    {
        const int arow = wid * 16 + (lane & 15);
        const int acol = (lane >> 4) * 8;
#pragma unroll
        for (int kb = 0; kb < 4; kb++) {
            uint32_t addr = sb + (uint32_t)((arow * LDA + kb * 16 + acol) * 2) + OQ;
            ldsm4(qh[kb][0], qh[kb][1], qh[kb][2], qh[kb][3], addr);
        }
    }

    float ofr[8][4];
#pragma unroll
    for (int j = 0; j < 8; j++)
#pragma unroll
        for (int q = 0; q < 4; q++) ofr[j][q] = 0.f;
    float mx0 = -1e30f, mx1 = -1e30f, ls0 = 0.f, ls1 = 0.f;
    const float scale = 0.125f;

    const int brow = ((lane >> 4) << 3) + (lane & 7);
    const int bcol = ((lane >> 3) & 1) * 8;

    for (int ch = 0; ch < 4; ch++) {
        __syncthreads();
        const int kbase = ch * 64;
        // K row-major (16B granules)
        {
            const uint4 z = make_uint4(0, 0, 0, 0);
            for (int idx = tid; idx < 64 * 8; idx += AT_T) {
                int r = idx >> 3, c8 = (idx & 7) * 8;
                int key = kbase + r;
                uint4 u = (key < Pdim) ? *(const uint4*)(g_k + base + (size_t)key * HD + c8) : z;
                *(uint4*)(Ks + r * LDA + c8) = u;
            }
        }
        // V transposed: vector load (8 halves along c), scattered smem stores
        for (int idx = tid; idx < 64 * 8; idx += AT_T) {
            int r = idx >> 3, c8 = (idx & 7) * 8;
            int key = kbase + r;
            if (key < Pdim) {
                uint4 u = *(const uint4*)(g_v + base + (size_t)key * HD + c8);
                const __half* hp = (const __half*)&u;
#pragma unroll
                for (int j = 0; j < 8; j++) Vt[(c8 + j) * LDA + r] = hp[j];
            } else {
                const __half z = __float2half(0.f);
#pragma unroll
                for (int j = 0; j < 8; j++) Vt[(c8 + j) * LDA + r] = z;
            }
        }
        __syncthreads();

        // S = Q K^T (single pass)
        float sfr[8][4];
#pragma unroll
        for (int j = 0; j < 8; j++)
#pragma unroll
            for (int q = 0; q < 4; q++) sfr[j][q] = 0.f;

#pragma unroll
        for (int kb = 0; kb < 4; kb++) {
#pragma unroll
            for (int p = 0; p < 4; p++) {
                uint32_t ka = sb + (uint32_t)(((p * 16 + brow) * LDA + kb * 16 + bcol) * 2) + OK;
                uint32_t bh0, bh1, bh2, bh3;
                ldsm4(bh0, bh1, bh2, bh3, ka);
                mma16816h(sfr[2 * p], qh[kb][0], qh[kb][1], qh[kb][2], qh[kb][3], bh0, bh1);
                mma16816h(sfr[2 * p + 1], qh[kb][0], qh[kb][1], qh[kb][2], qh[kb][3], bh2, bh3);
            }
        }

        const int nvalid = Pdim - kbase;
#pragma unroll
        for (int j = 0; j < 8; j++)
#pragma unroll
            for (int q = 0; q < 4; q++) {
                int key = j * 8 + 2 * tg + (q & 1);
                sfr[j][q] = (key < nvalid) ? sfr[j][q] * scale : -1e30f;
            }

        float rm0 = -1e30f, rm1 = -1e30f;
#pragma unroll
        for (int j = 0; j < 8; j++) {
            rm0 = fmaxf(rm0, fmaxf(sfr[j][0], sfr[j][1]));
            rm1 = fmaxf(rm1, fmaxf(sfr[j][2], sfr[j][3]));
        }
        rm0 = fmaxf(rm0, __shfl_xor_sync(0xFFFFFFFFu, rm0, 1));
        rm0 = fmaxf(rm0, __shfl_xor_sync(0xFFFFFFFFu, rm0, 2));
        rm1 = fmaxf(rm1, __shfl_xor_sync(0xFFFFFFFFu, rm1, 1));
        rm1 = fmaxf(rm1, __shfl_xor_sync(0xFFFFFFFFu, rm1, 2));
        float nm0 = fmaxf(mx0, rm0), nm1 = fmaxf(mx1, rm1);
        float c0 = __expf(mx0 - nm0), c1 = __expf(mx1 - nm1);
        mx0 = nm0; mx1 = nm1;
        ls0 *= c0; ls1 *= c1;
#pragma unroll
        for (int j = 0; j < 8; j++) {
            ofr[j][0] *= c0; ofr[j][1] *= c0;
            ofr[j][2] *= c1; ofr[j][3] *= c1;
        }

        float rs0 = 0.f, rs1 = 0.f;
#pragma unroll
        for (int j = 0; j < 8; j++) {
            float p0 = __expf(sfr[j][0] - nm0);
            float p1 = __expf(sfr[j][1] - nm0);
            float p2 = __expf(sfr[j][2] - nm1);
            float p3 = __expf(sfr[j][3] - nm1);
            rs0 += p0 + p1; rs1 += p2 + p3;
            sfr[j][0] = p0; sfr[j][1] = p1; sfr[j][2] = p2; sfr[j][3] = p3;
        }
        rs0 += __shfl_xor_sync(0xFFFFFFFFu, rs0, 1);
        rs0 += __shfl_xor_sync(0xFFFFFFFFu, rs0, 2);
        rs1 += __shfl_xor_sync(0xFFFFFFFFu, rs1, 1);
        rs1 += __shfl_xor_sync(0xFFFFFFFFu, rs1, 2);
        ls0 += rs0; ls1 += rs1;

        // PV: P split hi/lo (2-pass) against single V^T
#pragma unroll
        for (int kb = 0; kb < 4; kb++) {
            uint32_t pah[4], pal[4];
#pragma unroll
            for (int half = 0; half < 2; half++) {
                const int j = 2 * kb + half;
                float p0 = sfr[j][0], p1 = sfr[j][1], p2 = sfr[j][2], p3 = sfr[j][3];
                __half h0 = __float2half(p0);
                __half h1 = __float2half(p1);
                __half h2 = __float2half(p2);
                __half h3 = __float2half(p3);
                pah[2 * half + 0] = pack_h2(__half2float(h0), __half2float(h1));
                pah[2 * half + 1] = pack_h2(__half2float(h2), __half2float(h3));
                pal[2 * half + 0] = pack_h2(p0 - __half2float(h0), p1 - __half2float(h1));
                pal[2 * half + 1] = pack_h2(p2 - __half2float(h2), p3 - __half2float(h3));
            }
#pragma unroll
            for (int p = 0; p < 4; p++) {
                uint32_t va = sb + (uint32_t)(((p * 16 + brow) * LDA + kb * 16 + bcol) * 2) + OV;
                uint32_t vh0, vh1, vh2, vh3;
                ldsm4(vh0, vh1, vh2, vh3, va);
                mma16816h(ofr[2 * p], pah[0], pah[1], pah[2], pah[3], vh0, vh1);
                mma16816h(ofr[2 * p], pal[0], pal[1], pal[2], pal[3], vh0, vh1);
                mma16816h(ofr[2 * p + 1], pah[0], pah[1], pah[2], pah[3], vh2, vh3);
                mma16816h(ofr[2 * p + 1], pal[0], pal[1], pal[2], pal[3], vh2, vh3);
            }
        }
    }

    float inv0 = 1.f / ls0, inv1 = 1.f / ls1;
    const int r0 = wid * 16 + gq;
    const int r1 = r0 + 8;
    if (r0 < Pdim) {
        const size_t ob = ((size_t)b * Ndim + (f * Pdim + r0)) * Ddim + h * HD;
#pragma unroll
        for (int j = 0; j < 8; j++) {
            __half2 hv = __floats2half2_rn(ofr[j][0] * inv0, ofr[j][1] * inv0);
            *(__half2*)(g_wf + ob + j * 8 + 2 * tg) = hv;
        }
    }
    if (r1 < Pdim) {
        const size_t ob = ((size_t)b * Ndim + (f * Pdim + r1)) * Ddim + h * HD;
#pragma unroll
        for (int j = 0; j < 8; j++) {
            __half2 hv = __floats2half2_rn(ofr[j][2] * inv1, ofr[j][3] * inv1);
            *(__half2*)(g_wf + ob + j * 8 + 2 * tg) = hv;
        }
    }
}

// ---------------------------------------------------------------------------
// Temporal attention: heads 6..11, groups of 16 rows. fp16 q/k/v inputs,
// fp32 math, writes g_wf (fp16).
// ---------------------------------------------------------------------------
__global__ __launch_bounds__(128) void attn_temporal_k()
{
    int tid = blockIdx.x * 128 + threadIdx.x;
    const int TOT = Bdim * 6 * Ndim;
    if (tid >= TOT) return;
    int b = tid / (6 * Ndim);
    int rr = tid - b * (6 * Ndim);
    int h = 6 + rr / Ndim;
    int n = rr % Ndim;
    int n0 = n & ~15;
    size_t row = (((size_t)(b * Hh + h)) * Ndim + n) * HD;
    size_t gb  = (((size_t)(b * Hh + h)) * Ndim + n0) * HD;

    float qr[64];
    {
        const uint4* qp = (const uint4*)(g_q + row);
#pragma unroll
        for (int i = 0; i < 8; i++) {
            uint4 u = qp[i];
            const __half2* hp = (const __half2*)&u;
#pragma unroll
            for (int j = 0; j < 4; j++) {
                float2 t = __half22float2(hp[j]);
                qr[i * 8 + 2 * j] = t.x;
                qr[i * 8 + 2 * j + 1] = t.y;
            }
        }
    }

    float s[16];
    float mx = -1e30f;
#pragma unroll
    for (int f = 0; f < 16; f++) {
        const uint4* kp = (const uint4*)(g_k + gb + (size_t)f * HD);
        float a = 0.f;
#pragma unroll
        for (int i = 0; i < 8; i++) {
            uint4 u = kp[i];
            const __half2* hp = (const __half2*)&u;
#pragma unroll
            for (int j = 0; j < 4; j++) {
                float2 t = __half22float2(hp[j]);
                a = fmaf(qr[i * 8 + 2 * j], t.x, a);
                a = fmaf(qr[i * 8 + 2 * j + 1], t.y, a);
            }
        }
        s[f] = a * 0.125f;
        mx = fmaxf(mx, s[f]);
    }
    float lsum = 0.f;
#pragma unroll
    for (int f = 0; f < 16; f++) { s[f] = __expf(s[f] - mx); lsum += s[f]; }
    float inv = 1.f / lsum;
#pragma unroll
    for (int f = 0; f < 16; f++) s[f] *= inv;

    const size_t obase = ((size_t)b * Ndim + n) * Ddim + h * HD;
#pragma unroll
    for (int ch = 0; ch < 4; ch++) {
        float a16[16];
#pragma unroll
        for (int i = 0; i < 16; i++) a16[i] = 0.f;
#pragma unroll
        for (int f = 0; f < 16; f++) {
            float p = s[f];
            const uint4* vp = (const uint4*)(g_v + gb + (size_t)f * HD + ch * 16);
#pragma unroll
            for (int i = 0; i < 2; i++) {
                uint4 u = vp[i];
                const __half2* hp = (const __half2*)&u;
#pragma unroll
                for (int j = 0; j < 4; j++) {
                    float2 t = __half22float2(hp[j]);
                    a16[i * 8 + 2 * j]     = fmaf(p, t.x, a16[i * 8 + 2 * j]);
                    a16[i * 8 + 2 * j + 1] = fmaf(p, t.y, a16[i * 8 + 2 * j + 1]);
                }
            }
        }
#pragma unroll
        for (int i = 0; i < 8; i++) {
            __half2 hv = __floats2half2_rn(a16[2 * i], a16[2 * i + 1]);
            *(__half2*)(g_wf + obase + ch * 16 + 2 * i) = hv;
        }
    }
}

// ---------------------------------------------------------------------------
// Launch
// ---------------------------------------------------------------------------
extern "C" void kernel_launch(void* const* d_in, const int* in_sizes, int n_in,
                              void* d_out, int out_size)
{
    const float* x      = (const float*)d_in[0];
    const float* w_qkv  = (const float*)d_in[1];
    const float* w_proj = (const float*)d_in[2];
    const float* b_proj = (const float*)d_in[3];
    float* out = (float*)d_out;

    __half *p_q, *p_k, *p_v, *p_x, *p_wqkv, *p_wproj, *p_wf;
    cudaGetSymbolAddress((void**)&p_q, g_q);
    cudaGetSymbolAddress((void**)&p_k, g_k);
    cudaGetSymbolAddress((void**)&p_v, g_v);
    cudaGetSymbolAddress((void**)&p_x, g_x);
    cudaGetSymbolAddress((void**)&p_wqkv, g_wqkv);
    cudaGetSymbolAddress((void**)&p_wproj, g_wproj);
    cudaGetSymbolAddress((void**)&p_wf, g_wf);

    cudaFuncSetAttribute(tgemm_k, cudaFuncAttributeMaxDynamicSharedMemorySize, GSMEM);
    cudaFuncSetAttribute(attn_spatial_k, cudaFuncAttributeMaxDynamicSharedMemorySize, ATSMEM);

    // 0) fp16 conversions
    cvt_h<<<(unsigned)((MD_ELEMS + 255) / 256), 256>>>(x, p_x, MD_ELEMS);
    cvt_h<<<(unsigned)(((size_t)E3 * Ddim + 255) / 256), 256>>>(
        w_qkv, p_wqkv, (size_t)E3 * Ddim);
    cvt_h<<<(unsigned)(((size_t)Ddim * Ddim + 255) / 256), 256>>>(
        w_proj, p_wproj, (size_t)Ddim * Ddim);

    // 1) qkv GEMM (1-pass) with fused scatter into fp16 q/k/v head layout
    tgemm_k<<<dim3(E3 / 128, Mrows / 128), 256, GSMEM>>>(
        p_x, p_wqkv, nullptr, nullptr, E3, 0, p_q, p_k, p_v);

    // 2) MMA flash spatial attention (fp16)
    attn_spatial_k<<<768, AT_T, ATSMEM>>>();

    // 3) temporal attention
    attn_temporal_k<<<(Bdim * 6 * Ndim) / 128, 128>>>();

    // 4) out = wf @ w_proj^T + b_proj (1-pass)
    tgemm_k<<<dim3(Ddim / 128, Mrows / 128), 256, GSMEM>>>(
        p_wf, p_wproj, b_proj, out, Ddim, 1, nullptr, nullptr, nullptr);
}